// round 1
// baseline (speedup 1.0000x reference)
#include <cuda_runtime.h>
#include <cstddef>

// ---- problem constants ----
#define Bb   2
#define Ss   1568
#define Dd   768
#define Hh   12
#define HDd  64
#define Ff   8
#define NSP  196                 // spatial tokens per frame
#define BS   (Bb*Ss)             // 3136
#define BSD  (Bb*Ss*Dd)          // 2408448
#define XSZ  (Bb*Ss*Ff*Dd)       // 19267584
#define KVSZ (Bb*Ss*Ff*2*Dd)     // 38535168
#define SCALE 0.125f

// ---- scratch (no allocations allowed -> __device__ globals) ----
__device__ float g_q [BSD];
__device__ float g_k [BSD];
__device__ float g_v [BSD];
__device__ float g_xd[BSD];
__device__ float g_q2[BSD];
__device__ float g_t2[BSD];
__device__ float g_x [XSZ];
__device__ float g_kv[KVSZ];

// ============================================================
// Generic fp32 GEMM + bias: C[M,N] = A[M,K] @ W[K,N] + b
// 128x128 tile, BK=16, 256 threads, 8x8 register micro-tile.
// Requires: N % 128 == 0, K % 16 == 0. M guarded.
// ============================================================
__global__ __launch_bounds__(256) void gemm_bias_kernel(
    const float* __restrict__ A, const float* __restrict__ W,
    const float* __restrict__ bias, float* __restrict__ C,
    int M, int N, int K)
{
    __shared__ float As[16][128];
    __shared__ float Bs[16][128];

    const int tid = threadIdx.x;
    const int bm  = blockIdx.y * 128;
    const int bn  = blockIdx.x * 128;

    const int a_row  = tid >> 2;            // 0..63
    const int a_col4 = (tid & 3) << 2;      // 0,4,8,12
    const int b_row  = tid >> 5;            // 0..7
    const int b_col4 = (tid & 31) << 2;     // 0..124

    const int ty = tid >> 4, tx = tid & 15;

    float acc[8][8];
#pragma unroll
    for (int i = 0; i < 8; i++)
#pragma unroll
        for (int j = 0; j < 8; j++) acc[i][j] = 0.f;

    for (int k0 = 0; k0 < K; k0 += 16) {
#pragma unroll
        for (int i = 0; i < 2; i++) {
            int r  = a_row + i*64;
            int gm = bm + r;
            float4 v = make_float4(0.f,0.f,0.f,0.f);
            if (gm < M) v = *(const float4*)&A[(size_t)gm*K + k0 + a_col4];
            As[a_col4+0][r] = v.x;
            As[a_col4+1][r] = v.y;
            As[a_col4+2][r] = v.z;
            As[a_col4+3][r] = v.w;
        }
#pragma unroll
        for (int i = 0; i < 2; i++) {
            int r = b_row + i*8;
            float4 v = *(const float4*)&W[(size_t)(k0+r)*N + bn + b_col4];
            *(float4*)&Bs[r][b_col4] = v;
        }
        __syncthreads();

#pragma unroll
        for (int kk = 0; kk < 16; kk++) {
            float4 a0 = *(float4*)&As[kk][ty*8];
            float4 a1 = *(float4*)&As[kk][ty*8+4];
            float4 b0 = *(float4*)&Bs[kk][tx*8];
            float4 b1 = *(float4*)&Bs[kk][tx*8+4];
            float a[8] = {a0.x,a0.y,a0.z,a0.w,a1.x,a1.y,a1.z,a1.w};
            float b[8] = {b0.x,b0.y,b0.z,b0.w,b1.x,b1.y,b1.z,b1.w};
#pragma unroll
            for (int i = 0; i < 8; i++)
#pragma unroll
                for (int j = 0; j < 8; j++) acc[i][j] += a[i]*b[j];
        }
        __syncthreads();
    }

    float bz[8];
#pragma unroll
    for (int j = 0; j < 8; j++) bz[j] = bias[bn + tx*8 + j];

#pragma unroll
    for (int i = 0; i < 8; i++) {
        int gm = bm + ty*8 + i;
        if (gm < M) {
            size_t base = (size_t)gm*N + bn + tx*8;
            float4 o0 = make_float4(acc[i][0]+bz[0], acc[i][1]+bz[1],
                                    acc[i][2]+bz[2], acc[i][3]+bz[3]);
            float4 o1 = make_float4(acc[i][4]+bz[4], acc[i][5]+bz[5],
                                    acc[i][6]+bz[6], acc[i][7]+bz[7]);
            *(float4*)&C[base]   = o0;
            *(float4*)&C[base+4] = o1;
        }
    }
}

// ============================================================
// Stage 1: per (head, frame, 64-query tile) fused attention.
// scores = Qtile @ Kf^T  -> softmax(scale*.) over n=196
// -> write space_attn, x_tile = attn @ Vf
// smem: Q[64][64] | Kt[64][200] | V[196][64] | S[64][197]
// ============================================================
#define S1_SMEM_FLOATS (4096 + 64*200 + 196*64 + 64*197)   // 42048
#define S1_SMEM_BYTES  (S1_SMEM_FLOATS * 4)                // 168192

__global__ __launch_bounds__(256) void stage1_kernel(
    const float* __restrict__ Q, const float* __restrict__ K,
    const float* __restrict__ V, float* __restrict__ X,
    float* __restrict__ SA)
{
    extern __shared__ float sm[];
    float* sQ  = sm;            // [64][64]
    float* sKt = sm + 4096;     // [d=64][200] (196 used)
    float* sV  = sm + 16896;    // [196][64]
    float* sS  = sm + 29440;    // [64][197]

    const int tid = threadIdx.x;
    const int q0g = blockIdx.x * 64;
    const int f   = blockIdx.y;
    const int bh  = blockIdx.z;
    const int b   = bh / Hh, h = bh % Hh;

    // load Q tile (zero-pad OOB rows)
    for (int t = tid; t < 64*16; t += 256) {
        int r = t >> 4, dq = (t & 15) << 2;
        int qg = q0g + r;
        float4 v = make_float4(0.f,0.f,0.f,0.f);
        if (qg < Ss) v = *(const float4*)&Q[(size_t)(b*Ss + qg)*Dd + h*64 + dq];
        *(float4*)&sQ[r*64 + dq] = v;
    }
    // load K frame, transposed to [d][kk]
    for (int t = tid; t < NSP*16; t += 256) {
        int kk = t >> 4, dq = (t & 15) << 2;
        float4 v = *(const float4*)&K[(size_t)(b*Ss + f*NSP + kk)*Dd + h*64 + dq];
        sKt[(dq+0)*200 + kk] = v.x;
        sKt[(dq+1)*200 + kk] = v.y;
        sKt[(dq+2)*200 + kk] = v.z;
        sKt[(dq+3)*200 + kk] = v.w;
    }
    // load V frame
    for (int t = tid; t < NSP*16; t += 256) {
        int kk = t >> 4, dq = (t & 15) << 2;
        *(float4*)&sV[kk*64 + dq] =
            *(const float4*)&V[(size_t)(b*Ss + f*NSP + kk)*Dd + h*64 + dq];
    }
    __syncthreads();

    // scores: micro-tile 2q x 4k  (32*49 = 1568 micro-tiles)
    for (int t = tid; t < 32*49; t += 256) {
        int mq = t / 49, mk = t - mq*49;
        int q0 = mq*2, k0 = mk*4;
        float acc[2][4] = {{0,0,0,0},{0,0,0,0}};
        const float* qp = &sQ[q0*64];
#pragma unroll 8
        for (int d = 0; d < 64; d++) {
            float a0 = qp[d], a1 = qp[64+d];
            float4 kv4 = *(float4*)&sKt[d*200 + k0];
            acc[0][0] += a0*kv4.x; acc[0][1] += a0*kv4.y;
            acc[0][2] += a0*kv4.z; acc[0][3] += a0*kv4.w;
            acc[1][0] += a1*kv4.x; acc[1][1] += a1*kv4.y;
            acc[1][2] += a1*kv4.z; acc[1][3] += a1*kv4.w;
        }
#pragma unroll
        for (int i = 0; i < 2; i++)
#pragma unroll
            for (int j = 0; j < 4; j++)
                sS[(q0+i)*197 + k0 + j] = acc[i][j];
    }
    __syncthreads();

    // softmax over n=196, one warp per row, 8 rows/warp
    const int warp = tid >> 5, lane = tid & 31;
    for (int r = warp; r < 64; r += 8) {
        int qg = q0g + r;
        if (qg >= Ss) continue;
        float* row = &sS[r*197];
        float m = -1e30f;
        for (int j = lane; j < NSP; j += 32) m = fmaxf(m, row[j]);
#pragma unroll
        for (int o = 16; o > 0; o >>= 1) m = fmaxf(m, __shfl_xor_sync(0xffffffffu, m, o));
        float sum = 0.f;
        for (int j = lane; j < NSP; j += 32) {
            float e = __expf(SCALE*(row[j] - m));
            row[j] = e; sum += e;
        }
#pragma unroll
        for (int o = 16; o > 0; o >>= 1) sum += __shfl_xor_sync(0xffffffffu, sum, o);
        float inv = 1.f / sum;
        float* sap = &SA[((size_t)(bh*Ss + qg)*Ff + f)*NSP];
        for (int j = lane; j < NSP; j += 32) {
            float p = row[j]*inv;
            row[j] = p;
            sap[j] = p;
        }
    }
    __syncthreads();

    // x_tile = attn @ Vf : micro-tile 2q x 4d  (32*16 = 512 micro-tiles)
    for (int t = tid; t < 512; t += 256) {
        int dq = t & 15, mq = t >> 4;
        int q0 = mq*2, d0 = dq*4;
        float acc[2][4] = {{0,0,0,0},{0,0,0,0}};
#pragma unroll 4
        for (int n = 0; n < NSP; n++) {
            float s0 = sS[q0*197 + n];
            float s1 = sS[q0*197 + 197 + n];
            float4 v4 = *(float4*)&sV[n*64 + d0];
            acc[0][0] += s0*v4.x; acc[0][1] += s0*v4.y;
            acc[0][2] += s0*v4.z; acc[0][3] += s0*v4.w;
            acc[1][0] += s1*v4.x; acc[1][1] += s1*v4.y;
            acc[1][2] += s1*v4.z; acc[1][3] += s1*v4.w;
        }
#pragma unroll
        for (int i = 0; i < 2; i++) {
            int qg = q0g + q0 + i;
            if (qg < Ss)
                *(float4*)&X[((size_t)(b*Ss + qg)*Ff + f)*Dd + h*64 + d0] =
                    make_float4(acc[i][0], acc[i][1], acc[i][2], acc[i][3]);
        }
    }
}

// ============================================================
// Diagonal gather: x_diag[b, s, :] = x[b, s, s/196, :]
// float4 granularity.
// ============================================================
__global__ void diag_kernel(const float4* __restrict__ X4, float4* __restrict__ XD4)
{
    int idx = blockIdx.x * blockDim.x + threadIdx.x;
    if (idx >= BSD/4) return;
    int c4   = idx % (Dd/4);
    int rest = idx / (Dd/4);
    int s = rest % Ss;
    int b = rest / Ss;
    int f = s / NSP;
    XD4[idx] = X4[((size_t)(b*Ss + s)*Ff + f)*(Dd/4) + c4];
}

// ============================================================
// Stage 2: trajectory attention over F=8 frames.
// One warp per (b, s, h). Lane owns dims {lane, lane+32}.
// ============================================================
__global__ __launch_bounds__(128) void stage2_kernel(
    const float* __restrict__ Q2, const float* __restrict__ KV,
    float* __restrict__ T2)
{
    int gw = (blockIdx.x * blockDim.x + threadIdx.x) >> 5;
    if (gw >= BS*Hh) return;
    int h = gw % Hh;
    int s = (gw / Hh) % Ss;
    int b = gw / (Hh*Ss);
    int lane = threadIdx.x & 31;

    const float* q2p = Q2 + (size_t)(b*Ss + s)*Dd + h*64;
    float qa = q2p[lane], qb = q2p[lane+32];

    const float* kvp = KV + (size_t)(b*Ss + s)*Ff*2*Dd;

    float logit[Ff];
#pragma unroll
    for (int f = 0; f < Ff; f++) {
        const float* k2 = kvp + (size_t)f*2*Dd + h*64;
        float p = qa*k2[lane] + qb*k2[lane+32];
#pragma unroll
        for (int o = 16; o > 0; o >>= 1) p += __shfl_xor_sync(0xffffffffu, p, o);
        logit[f] = p * SCALE;
    }
    float m = logit[0];
#pragma unroll
    for (int f = 1; f < Ff; f++) m = fmaxf(m, logit[f]);
    float e[Ff], sum = 0.f;
#pragma unroll
    for (int f = 0; f < Ff; f++) { e[f] = __expf(logit[f]-m); sum += e[f]; }
    float inv = 1.f / sum;
    float oa = 0.f, ob = 0.f;
#pragma unroll
    for (int f = 0; f < Ff; f++) {
        const float* v2 = kvp + (size_t)f*2*Dd + Dd + h*64;
        float w = e[f]*inv;
        oa += w*v2[lane]; ob += w*v2[lane+32];
    }
    float* op = T2 + (size_t)(b*Ss + s)*Dd + h*64;
    op[lane] = oa; op[lane+32] = ob;
}

// ============================================================
// launch
// ============================================================
extern "C" void kernel_launch(void* const* d_in, const int* in_sizes, int n_in,
                              void* d_out, int out_size)
{
    const float* query = (const float*)d_in[0];
    const float* key_t = (const float*)d_in[1];
    const float* value = (const float*)d_in[2];
    const float* Wq   = (const float*)d_in[3];
    const float* bq   = (const float*)d_in[4];
    const float* Wk   = (const float*)d_in[5];
    const float* bk   = (const float*)d_in[6];
    const float* Wv   = (const float*)d_in[7];
    const float* bv   = (const float*)d_in[8];
    const float* Wpq  = (const float*)d_in[9];
    const float* bpq  = (const float*)d_in[10];
    const float* Wpkv = (const float*)d_in[11];
    const float* bpkv = (const float*)d_in[12];
    const float* Wp   = (const float*)d_in[13];
    const float* bp   = (const float*)d_in[14];

    float* out = (float*)d_out;            // (B, S, D)
    float* sa  = out + BSD;                // (B*H, S, F, n) space_attn

    float *q, *k, *v, *xd, *q2, *t2, *x, *kv;
    cudaGetSymbolAddress((void**)&q,  g_q);
    cudaGetSymbolAddress((void**)&k,  g_k);
    cudaGetSymbolAddress((void**)&v,  g_v);
    cudaGetSymbolAddress((void**)&xd, g_xd);
    cudaGetSymbolAddress((void**)&q2, g_q2);
    cudaGetSymbolAddress((void**)&t2, g_t2);
    cudaGetSymbolAddress((void**)&x,  g_x);
    cudaGetSymbolAddress((void**)&kv, g_kv);

    cudaFuncSetAttribute(stage1_kernel,
                         cudaFuncAttributeMaxDynamicSharedMemorySize, S1_SMEM_BYTES);

    dim3 gP(Dd/128, (BS+127)/128);     // (6, 25)
    dim3 gKV((2*Dd)/128, (BS*Ff)/128); // (12, 196)

    gemm_bias_kernel<<<gP, 256>>>(query, Wq, bq, q, BS, Dd, Dd);
    gemm_bias_kernel<<<gP, 256>>>(key_t, Wk, bk, k, BS, Dd, Dd);
    gemm_bias_kernel<<<gP, 256>>>(value, Wv, bv, v, BS, Dd, Dd);

    stage1_kernel<<<dim3(25, Ff, Bb*Hh), 256, S1_SMEM_BYTES>>>(q, k, v, x, sa);

    diag_kernel<<<(BSD/4 + 255)/256, 256>>>((const float4*)x, (float4*)xd);

    gemm_bias_kernel<<<gP, 256>>>(xd, Wpq, bpq, q2, BS, Dd, Dd);
    gemm_bias_kernel<<<gKV, 256>>>(x, Wpkv, bpkv, kv, BS*Ff, 2*Dd, Dd);

    stage2_kernel<<<(BS*Hh)/4, 128>>>(q2, kv, t2);

    gemm_bias_kernel<<<gP, 256>>>(t2, Wp, bp, out, BS, Dd, Dd);
}

// round 4
// speedup vs baseline: 1.6050x; 1.6050x over previous
#include <cuda_runtime.h>
#include <cuda_bf16.h>
#include <cstdint>
#include <cstddef>

// ---- problem constants ----
#define Bb   2
#define Ss   1568
#define Dd   768
#define Hh   12
#define HDd  64
#define Ff   8
#define NSP  196
#define BS   (Bb*Ss)             // 3136
#define BSD  (Bb*Ss*Dd)          // 2408448
#define XSZ  (Bb*Ss*Ff*Dd)       // 19267584
#define KVSZ (Bb*Ss*Ff*2*Dd)     // 38535168
#define SCALE 0.125f

// ---- scratch ----
__device__ float g_q [BSD];
__device__ float g_k [BSD];
__device__ float g_v [BSD];
__device__ float g_q2[BSD];
__device__ float g_kv[KVSZ];

// bf16 hi/lo planes for GEMM A operands
__device__ __align__(16) __nv_bfloat16 g_inqh[BSD], g_inql[BSD];
__device__ __align__(16) __nv_bfloat16 g_inkh[BSD], g_inkl[BSD];
__device__ __align__(16) __nv_bfloat16 g_invh[BSD], g_invl[BSD];
__device__ __align__(16) __nv_bfloat16 g_xh [XSZ], g_xl [XSZ];
__device__ __align__(16) __nv_bfloat16 g_xdh[BSD], g_xdl[BSD];
__device__ __align__(16) __nv_bfloat16 g_t2h[BSD], g_t2l[BSD];

// transposed+split weights: [N][K] bf16, hi and lo parts
#define WSQ  (768*768)
#define OFF_WQ   0
#define OFF_WK   (1*WSQ)
#define OFF_WV   (2*WSQ)
#define OFF_WPQ  (3*WSQ)
#define OFF_WP   (4*WSQ)
#define OFF_WPKV (5*WSQ)
#define WT_ELEMS (5*WSQ + 1536*768)
__device__ __align__(16) __nv_bfloat16 g_wth[WT_ELEMS];
__device__ __align__(16) __nv_bfloat16 g_wtl[WT_ELEMS];

// ============================================================
// helpers
// ============================================================
__device__ __forceinline__ uint32_t smem_u32(const void* p) {
    uint32_t a;
    asm("{ .reg .u64 t; cvta.to.shared.u64 t, %1; cvt.u32.u64 %0, t; }" : "=r"(a) : "l"(p));
    return a;
}
__device__ __forceinline__ void ldmx4(uint32_t* r, uint32_t a) {
    asm volatile("ldmatrix.sync.aligned.m8n8.x4.shared.b16 {%0,%1,%2,%3}, [%4];"
        : "=r"(r[0]), "=r"(r[1]), "=r"(r[2]), "=r"(r[3]) : "r"(a));
}
__device__ __forceinline__ void mma_bf16(float* c, const uint32_t* a, const uint32_t* b) {
    asm volatile("mma.sync.aligned.m16n8k16.row.col.f32.bf16.bf16.f32 "
        "{%0,%1,%2,%3}, {%4,%5,%6,%7}, {%8,%9}, {%0,%1,%2,%3};"
        : "+f"(c[0]), "+f"(c[1]), "+f"(c[2]), "+f"(c[3])
        : "r"(a[0]), "r"(a[1]), "r"(a[2]), "r"(a[3]), "r"(b[0]), "r"(b[1]));
}
#define CP_ASYNC16(dst, src, sz) \
    asm volatile("cp.async.cg.shared.global [%0], [%1], 16, %2;" \
                 :: "r"(dst), "l"(src), "r"(sz))
#define CP_COMMIT() asm volatile("cp.async.commit_group;" ::: "memory")
#define CP_WAIT(n)  asm volatile("cp.async.wait_group %0;" :: "n"(n) : "memory")

__device__ __forceinline__ void split2(float a, float b, uint32_t& h, uint32_t& l) {
    __nv_bfloat162 hh = __floats2bfloat162_rn(a, b);
    float2 f = __bfloat1622float2(hh);
    __nv_bfloat162 ll = __floats2bfloat162_rn(a - f.x, b - f.y);
    h = *(uint32_t*)&hh; l = *(uint32_t*)&ll;
}

// ============================================================
// Weight transpose + bf16 split: W[K][N] fp32 -> hi/lo [N][K] bf16
// ============================================================
__global__ void wtrans_kernel(const float* __restrict__ W,
                              __nv_bfloat16* __restrict__ hi,
                              __nv_bfloat16* __restrict__ lo, int K, int N)
{
    __shared__ float t[32][33];
    int n0 = blockIdx.x * 32, k0 = blockIdx.y * 32;
    int tx = threadIdx.x, ty = threadIdx.y;
#pragma unroll
    for (int i = 0; i < 32; i += 8)
        t[ty + i][tx] = W[(size_t)(k0 + ty + i) * N + n0 + tx];
    __syncthreads();
#pragma unroll
    for (int i = 0; i < 32; i += 8) {
        float v = t[tx][ty + i];
        __nv_bfloat16 h = __float2bfloat16(v);
        __nv_bfloat16 l = __float2bfloat16(v - __bfloat162float(h));
        size_t o = (size_t)(n0 + ty + i) * K + k0 + tx;
        hi[o] = h; lo[o] = l;
    }
}

// ============================================================
// elementwise fp32 -> bf16 hi/lo planes
// ============================================================
__global__ void split_kernel(const float4* __restrict__ in,
                             uint2* __restrict__ H, uint2* __restrict__ L, int n4)
{
    int i = blockIdx.x * blockDim.x + threadIdx.x;
    if (i >= n4) return;
    float4 a = in[i];
    uint32_t h01, l01, h23, l23;
    split2(a.x, a.y, h01, l01);
    split2(a.z, a.w, h23, l23);
    H[i] = make_uint2(h01, h23);
    L[i] = make_uint2(l01, l23);
}

// ============================================================
// HMMA bf16x3 GEMM + bias: C[M,N] = (Ah+Al)[M,K] @ (Bh+Bl)[N,K]^T + bias
// 128x128 tile, BK=32, 256 thr, 2-stage cp.async pipeline.
// smem rows padded to 80B (conflict-free for ldmatrix + cp.async).
// ============================================================
#define GST 40960                       // bytes per stage (4 planes x 128 x 80)
#define G_SMEM_BYTES (2*GST)            // 81920

__global__ __launch_bounds__(256) void gemm_hmma_kernel(
    const __nv_bfloat16* __restrict__ Ah, const __nv_bfloat16* __restrict__ Al,
    const __nv_bfloat16* __restrict__ Bh, const __nv_bfloat16* __restrict__ Bl,
    const float* __restrict__ bias, float* __restrict__ C,
    int M, int N, int K)
{
    extern __shared__ char smem[];
    const uint32_t sb = smem_u32(smem);
    const int tid = threadIdx.x;
    const int wid = tid >> 5, lane = tid & 31;
    const int bm = blockIdx.y * 128, bn = blockIdx.x * 128;

    const int m0 = (wid & 3) * 32;      // warp m offset in tile
    const int n0 = (wid >> 2) * 64;     // warp n offset in tile

    float c[2][8][4];
#pragma unroll
    for (int i = 0; i < 2; i++)
#pragma unroll
        for (int j = 0; j < 8; j++)
#pragma unroll
            for (int e = 0; e < 4; e++) c[i][j][e] = 0.f;

    // ldmatrix lane address components
    const int ra = (lane & 7) + ((lane >> 3) & 1) * 8;   // A row-in-atom
    const int ca = (lane >> 4) & 1;                      // A k16-half
    const int rb = (lane & 7) + ((lane >> 4) & 1) * 8;   // B row-in-pair
    const int cb = (lane >> 3) & 1;                      // B k16-half

    // ---- async load issue for stage s, k-block kb ----
    auto issue = [&](int kb, int s) {
#pragma unroll
        for (int i = 0; i < 8; i++) {
            int id  = i * 256 + tid;          // 0..2047
            int p   = id >> 9;                // plane 0..3
            int rem = id & 511;
            int row = rem >> 2, c4 = rem & 3;
            uint32_t dst = sb + s * GST + p * 10240 + row * 80 + c4 * 16;
            uint32_t sz = 16;
            const __nv_bfloat16* src;
            if (p < 2) {
                int gm = bm + row;
                int g  = gm < M ? gm : 0;
                if (gm >= M) sz = 0;
                src = (p == 0 ? Ah : Al) + (size_t)g * K + kb + c4 * 8;
            } else {
                src = (p == 2 ? Bh : Bl) + (size_t)(bn + row) * K + kb + c4 * 8;
            }
            CP_ASYNC16(dst, src, sz);
        }
    };

    issue(0, 0);
    CP_COMMIT();

    int s = 0;
    for (int kb = 0; kb < K; kb += 32, s ^= 1) {
        if (kb + 32 < K) {
            issue(kb + 32, s ^ 1);
            CP_COMMIT();
            CP_WAIT(1);
        } else {
            CP_WAIT(0);
        }
        __syncthreads();

        uint32_t base = sb + s * GST;
        uint32_t aAh = base +     0 + (m0 + ra) * 80 + ca * 16;
        uint32_t aAl = base + 10240 + (m0 + ra) * 80 + ca * 16;
        uint32_t aBh = base + 20480 + (n0 + rb) * 80 + cb * 16;
        uint32_t aBl = base + 30720 + (n0 + rb) * 80 + cb * 16;

#pragma unroll
        for (int ks = 0; ks < 2; ks++) {
            uint32_t ah[2][4], al[2][4], bh[4][4], bl[4][4];
            ldmx4(ah[0], aAh + ks * 32);
            ldmx4(ah[1], aAh + 16 * 80 + ks * 32);
            ldmx4(al[0], aAl + ks * 32);
            ldmx4(al[1], aAl + 16 * 80 + ks * 32);
#pragma unroll
            for (int j = 0; j < 4; j++) {
                ldmx4(bh[j], aBh + j * 16 * 80 + ks * 32);
                ldmx4(bl[j], aBl + j * 16 * 80 + ks * 32);
            }
#pragma unroll
            for (int mi = 0; mi < 2; mi++)
#pragma unroll
                for (int nj = 0; nj < 8; nj++) {
                    const uint32_t* bhp = &bh[nj >> 1][(nj & 1) * 2];
                    const uint32_t* blp = &bl[nj >> 1][(nj & 1) * 2];
                    mma_bf16(c[mi][nj], ah[mi], bhp);
                    mma_bf16(c[mi][nj], al[mi], bhp);
                    mma_bf16(c[mi][nj], ah[mi], blp);
                }
        }
        __syncthreads();
    }

    // ---- epilogue ----
    const int cr = lane >> 2, cc = (lane & 3) * 2;
#pragma unroll
    for (int nj = 0; nj < 8; nj++) {
        int bcol = bn + n0 + nj * 8 + cc;
        float b0 = bias[bcol], b1 = bias[bcol + 1];
#pragma unroll
        for (int mi = 0; mi < 2; mi++) {
            int r0 = bm + m0 + mi * 16 + cr;
            if (r0 < M)
                *(float2*)&C[(size_t)r0 * N + bcol] =
                    make_float2(c[mi][nj][0] + b0, c[mi][nj][1] + b1);
            int r1 = r0 + 8;
            if (r1 < M)
                *(float2*)&C[(size_t)r1 * N + bcol] =
                    make_float2(c[mi][nj][2] + b0, c[mi][nj][3] + b1);
        }
    }
}

// ============================================================
// Stage 1: fused per (head, frame, 64-q tile) attention.
// Writes X directly as bf16 hi/lo planes.
// ============================================================
#define S1_SMEM_FLOATS (4096 + 64*200 + 196*64 + 64*197)
#define S1_SMEM_BYTES  (S1_SMEM_FLOATS * 4)

__global__ __launch_bounds__(256) void stage1_kernel(
    const float* __restrict__ Q, const float* __restrict__ K,
    const float* __restrict__ V,
    uint2* __restrict__ XH, uint2* __restrict__ XL,
    float* __restrict__ SA)
{
    extern __shared__ float sm[];
    float* sQ  = sm;
    float* sKt = sm + 4096;
    float* sV  = sm + 16896;
    float* sS  = sm + 29440;

    const int tid = threadIdx.x;
    const int q0g = blockIdx.x * 64;
    const int f   = blockIdx.y;
    const int bh  = blockIdx.z;
    const int b   = bh / Hh, h = bh % Hh;

    for (int t = tid; t < 64*16; t += 256) {
        int r = t >> 4, dq = (t & 15) << 2;
        int qg = q0g + r;
        float4 v = make_float4(0.f,0.f,0.f,0.f);
        if (qg < Ss) v = *(const float4*)&Q[(size_t)(b*Ss + qg)*Dd + h*64 + dq];
        *(float4*)&sQ[r*64 + dq] = v;
    }
    for (int t = tid; t < NSP*16; t += 256) {
        int kk = t >> 4, dq = (t & 15) << 2;
        float4 v = *(const float4*)&K[(size_t)(b*Ss + f*NSP + kk)*Dd + h*64 + dq];
        sKt[(dq+0)*200 + kk] = v.x;
        sKt[(dq+1)*200 + kk] = v.y;
        sKt[(dq+2)*200 + kk] = v.z;
        sKt[(dq+3)*200 + kk] = v.w;
    }
    for (int t = tid; t < NSP*16; t += 256) {
        int kk = t >> 4, dq = (t & 15) << 2;
        *(float4*)&sV[kk*64 + dq] =
            *(const float4*)&V[(size_t)(b*Ss + f*NSP + kk)*Dd + h*64 + dq];
    }
    __syncthreads();

    for (int t = tid; t < 32*49; t += 256) {
        int mq = t / 49, mk = t - mq*49;
        int q0 = mq*2, k0 = mk*4;
        float acc[2][4] = {{0,0,0,0},{0,0,0,0}};
        const float* qp = &sQ[q0*64];
#pragma unroll 8
        for (int d = 0; d < 64; d++) {
            float a0 = qp[d], a1 = qp[64+d];
            float4 kv4 = *(float4*)&sKt[d*200 + k0];
            acc[0][0] += a0*kv4.x; acc[0][1] += a0*kv4.y;
            acc[0][2] += a0*kv4.z; acc[0][3] += a0*kv4.w;
            acc[1][0] += a1*kv4.x; acc[1][1] += a1*kv4.y;
            acc[1][2] += a1*kv4.z; acc[1][3] += a1*kv4.w;
        }
#pragma unroll
        for (int i = 0; i < 2; i++)
#pragma unroll
            for (int j = 0; j < 4; j++)
                sS[(q0+i)*197 + k0 + j] = acc[i][j];
    }
    __syncthreads();

    const int warp = tid >> 5, lane = tid & 31;
    for (int r = warp; r < 64; r += 8) {
        int qg = q0g + r;
        if (qg >= Ss) continue;
        float* row = &sS[r*197];
        float m = -1e30f;
        for (int j = lane; j < NSP; j += 32) m = fmaxf(m, row[j]);
#pragma unroll
        for (int o = 16; o > 0; o >>= 1) m = fmaxf(m, __shfl_xor_sync(0xffffffffu, m, o));
        float sum = 0.f;
        for (int j = lane; j < NSP; j += 32) {
            float e = __expf(SCALE*(row[j] - m));
            row[j] = e; sum += e;
        }
#pragma unroll
        for (int o = 16; o > 0; o >>= 1) sum += __shfl_xor_sync(0xffffffffu, sum, o);
        float inv = 1.f / sum;
        float* sap = &SA[((size_t)(bh*Ss + qg)*Ff + f)*NSP];
        for (int j = lane; j < NSP; j += 32) {
            float p = row[j]*inv;
            row[j] = p;
            sap[j] = p;
        }
    }
    __syncthreads();

    for (int t = tid; t < 512; t += 256) {
        int dq = t & 15, mq = t >> 4;
        int q0 = mq*2, d0 = dq*4;
        float acc[2][4] = {{0,0,0,0},{0,0,0,0}};
#pragma unroll 4
        for (int n = 0; n < NSP; n++) {
            float s0 = sS[q0*197 + n];
            float s1 = sS[q0*197 + 197 + n];
            float4 v4 = *(float4*)&sV[n*64 + d0];
            acc[0][0] += s0*v4.x; acc[0][1] += s0*v4.y;
            acc[0][2] += s0*v4.z; acc[0][3] += s0*v4.w;
            acc[1][0] += s1*v4.x; acc[1][1] += s1*v4.y;
            acc[1][2] += s1*v4.z; acc[1][3] += s1*v4.w;
        }
#pragma unroll
        for (int i = 0; i < 2; i++) {
            int qg = q0g + q0 + i;
            if (qg < Ss) {
                uint32_t h01, l01, h23, l23;
                split2(acc[i][0], acc[i][1], h01, l01);
                split2(acc[i][2], acc[i][3], h23, l23);
                size_t eo = (((size_t)(b*Ss + qg)*Ff + f)*Dd + h*64 + d0) >> 2;
                XH[eo] = make_uint2(h01, h23);
                XL[eo] = make_uint2(l01, l23);
            }
        }
    }
}

// ============================================================
// Diagonal gather on bf16 planes: xd[b,s,:] = x[b,s,s/196,:]
// ============================================================
__global__ void diag_kernel(const uint2* __restrict__ XH, const uint2* __restrict__ XL,
                            uint2* __restrict__ XDH, uint2* __restrict__ XDL)
{
    int idx = blockIdx.x * blockDim.x + threadIdx.x;
    if (idx >= BSD/4) return;
    int c4   = idx % (Dd/4);
    int rest = idx / (Dd/4);
    int s = rest % Ss;
    int b = rest / Ss;
    int f = s / NSP;
    size_t src = ((size_t)(b*Ss + s)*Ff + f)*(Dd/4) + c4;
    XDH[idx] = XH[src];
    XDL[idx] = XL[src];
}

// ============================================================
// Stage 2: trajectory attention over F=8 frames.
// Writes t2 as bf16 hi/lo planes.
// ============================================================
__global__ __launch_bounds__(128) void stage2_kernel(
    const float* __restrict__ Q2, const float* __restrict__ KV,
    __nv_bfloat16* __restrict__ T2H, __nv_bfloat16* __restrict__ T2L)
{
    int gw = (blockIdx.x * blockDim.x + threadIdx.x) >> 5;
    if (gw >= BS*Hh) return;
    int h = gw % Hh;
    int s = (gw / Hh) % Ss;
    int b = gw / (Hh*Ss);
    int lane = threadIdx.x & 31;

    const float* q2p = Q2 + (size_t)(b*Ss + s)*Dd + h*64;
    float qa = q2p[lane], qb = q2p[lane+32];

    const float* kvp = KV + (size_t)(b*Ss + s)*Ff*2*Dd;

    float logit[Ff];
#pragma unroll
    for (int f = 0; f < Ff; f++) {
        const float* k2 = kvp + (size_t)f*2*Dd + h*64;
        float p = qa*k2[lane] + qb*k2[lane+32];
#pragma unroll
        for (int o = 16; o > 0; o >>= 1) p += __shfl_xor_sync(0xffffffffu, p, o);
        logit[f] = p * SCALE;
    }
    float m = logit[0];
#pragma unroll
    for (int f = 1; f < Ff; f++) m = fmaxf(m, logit[f]);
    float e[Ff], sum = 0.f;
#pragma unroll
    for (int f = 0; f < Ff; f++) { e[f] = __expf(logit[f]-m); sum += e[f]; }
    float inv = 1.f / sum;
    float oa = 0.f, ob = 0.f;
#pragma unroll
    for (int f = 0; f < Ff; f++) {
        const float* v2 = kvp + (size_t)f*2*Dd + Dd + h*64;
        float w = e[f]*inv;
        oa += w*v2[lane]; ob += w*v2[lane+32];
    }
    size_t off = (size_t)(b*Ss + s)*Dd + h*64;
    __nv_bfloat16 ha = __float2bfloat16(oa);
    __nv_bfloat16 hb = __float2bfloat16(ob);
    T2H[off + lane]      = ha;
    T2H[off + lane + 32] = hb;
    T2L[off + lane]      = __float2bfloat16(oa - __bfloat162float(ha));
    T2L[off + lane + 32] = __float2bfloat16(ob - __bfloat162float(hb));
}

// ============================================================
// launch
// ============================================================
extern "C" void kernel_launch(void* const* d_in, const int* in_sizes, int n_in,
                              void* d_out, int out_size)
{
    const float* query = (const float*)d_in[0];
    const float* key_t = (const float*)d_in[1];
    const float* value = (const float*)d_in[2];
    const float* Wq   = (const float*)d_in[3];
    const float* bq   = (const float*)d_in[4];
    const float* Wk   = (const float*)d_in[5];
    const float* bk   = (const float*)d_in[6];
    const float* Wv   = (const float*)d_in[7];
    const float* bv   = (const float*)d_in[8];
    const float* Wpq  = (const float*)d_in[9];
    const float* bpq  = (const float*)d_in[10];
    const float* Wpkv = (const float*)d_in[11];
    const float* bpkv = (const float*)d_in[12];
    const float* Wp   = (const float*)d_in[13];
    const float* bp   = (const float*)d_in[14];

    float* out = (float*)d_out;            // (B, S, D)
    float* sa  = out + BSD;                // (B*H, S, F, n)

    float *q, *k, *v, *q2, *kv;
    __nv_bfloat16 *wth, *wtl;
    __nv_bfloat16 *inqh, *inql, *inkh, *inkl, *invh, *invl;
    __nv_bfloat16 *xh, *xl, *xdh, *xdl, *t2h, *t2l;
    cudaGetSymbolAddress((void**)&q,   g_q);
    cudaGetSymbolAddress((void**)&k,   g_k);
    cudaGetSymbolAddress((void**)&v,   g_v);
    cudaGetSymbolAddress((void**)&q2,  g_q2);
    cudaGetSymbolAddress((void**)&kv,  g_kv);
    cudaGetSymbolAddress((void**)&wth, g_wth);
    cudaGetSymbolAddress((void**)&wtl, g_wtl);
    cudaGetSymbolAddress((void**)&inqh, g_inqh);
    cudaGetSymbolAddress((void**)&inql, g_inql);
    cudaGetSymbolAddress((void**)&inkh, g_inkh);
    cudaGetSymbolAddress((void**)&inkl, g_inkl);
    cudaGetSymbolAddress((void**)&invh, g_invh);
    cudaGetSymbolAddress((void**)&invl, g_invl);
    cudaGetSymbolAddress((void**)&xh,  g_xh);
    cudaGetSymbolAddress((void**)&xl,  g_xl);
    cudaGetSymbolAddress((void**)&xdh, g_xdh);
    cudaGetSymbolAddress((void**)&xdl, g_xdl);
    cudaGetSymbolAddress((void**)&t2h, g_t2h);
    cudaGetSymbolAddress((void**)&t2l, g_t2l);

    cudaFuncSetAttribute(stage1_kernel,
                         cudaFuncAttributeMaxDynamicSharedMemorySize, S1_SMEM_BYTES);
    cudaFuncSetAttribute(gemm_hmma_kernel,
                         cudaFuncAttributeMaxDynamicSharedMemorySize, G_SMEM_BYTES);

    // ---- weight transpose + split ----
    dim3 wb(32, 8);
    wtrans_kernel<<<dim3(24,24), wb>>>(Wq,   wth+OFF_WQ,   wtl+OFF_WQ,   768, 768);
    wtrans_kernel<<<dim3(24,24), wb>>>(Wk,   wth+OFF_WK,   wtl+OFF_WK,   768, 768);
    wtrans_kernel<<<dim3(24,24), wb>>>(Wv,   wth+OFF_WV,   wtl+OFF_WV,   768, 768);
    wtrans_kernel<<<dim3(24,24), wb>>>(Wpq,  wth+OFF_WPQ,  wtl+OFF_WPQ,  768, 768);
    wtrans_kernel<<<dim3(24,24), wb>>>(Wp,   wth+OFF_WP,   wtl+OFF_WP,   768, 768);
    wtrans_kernel<<<dim3(48,24), wb>>>(Wpkv, wth+OFF_WPKV, wtl+OFF_WPKV, 768, 1536);

    // ---- split fp32 inputs to bf16 planes ----
    int n4 = BSD/4, sg = (n4 + 255)/256;
    split_kernel<<<sg, 256>>>((const float4*)query, (uint2*)inqh, (uint2*)inql, n4);
    split_kernel<<<sg, 256>>>((const float4*)key_t, (uint2*)inkh, (uint2*)inkl, n4);
    split_kernel<<<sg, 256>>>((const float4*)value, (uint2*)invh, (uint2*)invl, n4);

    dim3 gP(6, 25);       // N=768, M=3136
    dim3 gKV(12, 196);    // N=1536, M=25088

    gemm_hmma_kernel<<<gP, 256, G_SMEM_BYTES>>>(inqh, inql, wth+OFF_WQ, wtl+OFF_WQ, bq, q, BS, 768, 768);
    gemm_hmma_kernel<<<gP, 256, G_SMEM_BYTES>>>(inkh, inkl, wth+OFF_WK, wtl+OFF_WK, bk, k, BS, 768, 768);
    gemm_hmma_kernel<<<gP, 256, G_SMEM_BYTES>>>(invh, invl, wth+OFF_WV, wtl+OFF_WV, bv, v, BS, 768, 768);

    stage1_kernel<<<dim3(25, Ff, Bb*Hh), 256, S1_SMEM_BYTES>>>(
        q, k, v, (uint2*)xh, (uint2*)xl, sa);

    diag_kernel<<<(BSD/4 + 255)/256, 256>>>(
        (const uint2*)xh, (const uint2*)xl, (uint2*)xdh, (uint2*)xdl);

    gemm_hmma_kernel<<<gP, 256, G_SMEM_BYTES>>>(xdh, xdl, wth+OFF_WPQ, wtl+OFF_WPQ, bpq, q2, BS, 768, 768);
    gemm_hmma_kernel<<<gKV, 256, G_SMEM_BYTES>>>(xh, xl, wth+OFF_WPKV, wtl+OFF_WPKV, bpkv, kv, BS*Ff, 1536, 768);

    stage2_kernel<<<(BS*Hh)/4, 128>>>(q2, kv, t2h, t2l);

    gemm_hmma_kernel<<<gP, 256, G_SMEM_BYTES>>>(t2h, t2l, wth+OFF_WP, wtl+OFF_WP, bp, out, BS, 768, 768);
}

// round 6
// speedup vs baseline: 2.5418x; 1.5837x over previous
#include <cuda_runtime.h>
#include <cuda_bf16.h>
#include <cstdint>
#include <cstddef>

// ---- problem constants ----
#define Bb   2
#define Ss   1568
#define Dd   768
#define Hh   12
#define HDd  64
#define Ff   8
#define NSP  196
#define BS   (Bb*Ss)             // 3136
#define BSD  (Bb*Ss*Dd)          // 2408448
#define XSZ  (Bb*Ss*Ff*Dd)       // 19267584
#define KVSZ (Bb*Ss*Ff*2*Dd)     // 38535168
#define SCALE 0.125f

// ---- scratch ----
__device__ float g_q2[BSD];
__device__ float g_kv[KVSZ];

// bf16 hi/lo planes
__device__ __align__(16) __nv_bfloat16 g_inqh[BSD], g_inql[BSD];
__device__ __align__(16) __nv_bfloat16 g_inkh[BSD], g_inkl[BSD];
__device__ __align__(16) __nv_bfloat16 g_invh[BSD], g_invl[BSD];
__device__ __align__(16) __nv_bfloat16 g_qph[BSD], g_qpl[BSD];   // projected q
__device__ __align__(16) __nv_bfloat16 g_kph[BSD], g_kpl[BSD];   // projected k
__device__ __align__(16) __nv_bfloat16 g_vph[BSD], g_vpl[BSD];   // projected v
__device__ __align__(16) __nv_bfloat16 g_xh [XSZ], g_xl [XSZ];
__device__ __align__(16) __nv_bfloat16 g_xdh[BSD], g_xdl[BSD];
__device__ __align__(16) __nv_bfloat16 g_t2h[BSD], g_t2l[BSD];

// transposed+split weights: [N][K] bf16, hi and lo parts
#define WSQ  (768*768)
#define OFF_WQ   0
#define OFF_WK   (1*WSQ)
#define OFF_WV   (2*WSQ)
#define OFF_WPQ  (3*WSQ)
#define OFF_WP   (4*WSQ)
#define OFF_WPKV (5*WSQ)
#define WT_ELEMS (5*WSQ + 1536*768)
__device__ __align__(16) __nv_bfloat16 g_wth[WT_ELEMS];
__device__ __align__(16) __nv_bfloat16 g_wtl[WT_ELEMS];

// ============================================================
// helpers
// ============================================================
__device__ __forceinline__ uint32_t smem_u32(const void* p) {
    uint32_t a;
    asm("{ .reg .u64 t; cvta.to.shared.u64 t, %1; cvt.u32.u64 %0, t; }" : "=r"(a) : "l"(p));
    return a;
}
__device__ __forceinline__ void ldmx4(uint32_t* r, uint32_t a) {
    asm volatile("ldmatrix.sync.aligned.m8n8.x4.shared.b16 {%0,%1,%2,%3}, [%4];"
        : "=r"(r[0]), "=r"(r[1]), "=r"(r[2]), "=r"(r[3]) : "r"(a));
}
__device__ __forceinline__ void ldmx4t(uint32_t* r, uint32_t a) {
    asm volatile("ldmatrix.sync.aligned.m8n8.x4.trans.shared.b16 {%0,%1,%2,%3}, [%4];"
        : "=r"(r[0]), "=r"(r[1]), "=r"(r[2]), "=r"(r[3]) : "r"(a));
}
__device__ __forceinline__ void mma_bf16(float* c, const uint32_t* a, const uint32_t* b) {
    asm volatile("mma.sync.aligned.m16n8k16.row.col.f32.bf16.bf16.f32 "
        "{%0,%1,%2,%3}, {%4,%5,%6,%7}, {%8,%9}, {%0,%1,%2,%3};"
        : "+f"(c[0]), "+f"(c[1]), "+f"(c[2]), "+f"(c[3])
        : "r"(a[0]), "r"(a[1]), "r"(a[2]), "r"(a[3]), "r"(b[0]), "r"(b[1]));
}
#define CP_ASYNC16(dst, src, sz) \
    asm volatile("cp.async.cg.shared.global [%0], [%1], 16, %2;" \
                 :: "r"(dst), "l"(src), "r"(sz))
#define CP_COMMIT() asm volatile("cp.async.commit_group;" ::: "memory")
#define CP_WAIT(n)  asm volatile("cp.async.wait_group %0;" :: "n"(n) : "memory")

__device__ __forceinline__ void split2(float a, float b, uint32_t& h, uint32_t& l) {
    __nv_bfloat162 hh = __floats2bfloat162_rn(a, b);
    float2 f = __bfloat1622float2(hh);
    __nv_bfloat162 ll = __floats2bfloat162_rn(a - f.x, b - f.y);
    h = *(uint32_t*)&hh; l = *(uint32_t*)&ll;
}

// ============================================================
// Weight transpose + bf16 split: W[K][N] fp32 -> hi/lo [N][K] bf16
// ============================================================
__global__ void wtrans_kernel(const float* __restrict__ W,
                              __nv_bfloat16* __restrict__ hi,
                              __nv_bfloat16* __restrict__ lo, int K, int N)
{
    __shared__ float t[32][33];
    int n0 = blockIdx.x * 32, k0 = blockIdx.y * 32;
    int tx = threadIdx.x, ty = threadIdx.y;
#pragma unroll
    for (int i = 0; i < 32; i += 8)
        t[ty + i][tx] = W[(size_t)(k0 + ty + i) * N + n0 + tx];
    __syncthreads();
#pragma unroll
    for (int i = 0; i < 32; i += 8) {
        float v = t[tx][ty + i];
        __nv_bfloat16 h = __float2bfloat16(v);
        __nv_bfloat16 l = __float2bfloat16(v - __bfloat162float(h));
        size_t o = (size_t)(n0 + ty + i) * K + k0 + tx;
        hi[o] = h; lo[o] = l;
    }
}

// ============================================================
// elementwise fp32 -> bf16 hi/lo planes
// ============================================================
__global__ void split_kernel(const float4* __restrict__ in,
                             uint2* __restrict__ H, uint2* __restrict__ L, int n4)
{
    int i = blockIdx.x * blockDim.x + threadIdx.x;
    if (i >= n4) return;
    float4 a = in[i];
    uint32_t h01, l01, h23, l23;
    split2(a.x, a.y, h01, l01);
    split2(a.z, a.w, h23, l23);
    H[i] = make_uint2(h01, h23);
    L[i] = make_uint2(l01, l23);
}

// ============================================================
// HMMA bf16x3 GEMM core (shared by fp32-out and split-out variants)
// ============================================================
#define GST 40960
#define G_SMEM_BYTES (2*GST)

template <int OUT_SPLIT>
__device__ __forceinline__ void gemm_body(
    const __nv_bfloat16* __restrict__ Ah, const __nv_bfloat16* __restrict__ Al,
    const __nv_bfloat16* __restrict__ Bh, const __nv_bfloat16* __restrict__ Bl,
    const float* __restrict__ bias,
    float* __restrict__ C, __nv_bfloat16* __restrict__ CH, __nv_bfloat16* __restrict__ CL,
    int M, int N, int K)
{
    extern __shared__ char smem[];
    const uint32_t sb = smem_u32(smem);
    const int tid = threadIdx.x;
    const int wid = tid >> 5, lane = tid & 31;
    const int bm = blockIdx.y * 128, bn = blockIdx.x * 128;
    const int m0 = (wid & 3) * 32;
    const int n0 = (wid >> 2) * 64;

    float c[2][8][4];
#pragma unroll
    for (int i = 0; i < 2; i++)
#pragma unroll
        for (int j = 0; j < 8; j++)
#pragma unroll
            for (int e = 0; e < 4; e++) c[i][j][e] = 0.f;

    const int ra = (lane & 7) + ((lane >> 3) & 1) * 8;
    const int ca = (lane >> 4) & 1;
    const int rb = (lane & 7) + ((lane >> 4) & 1) * 8;
    const int cb = (lane >> 3) & 1;

    auto issue = [&](int kb, int s) {
#pragma unroll
        for (int i = 0; i < 8; i++) {
            int id  = i * 256 + tid;
            int p   = id >> 9;
            int rem = id & 511;
            int row = rem >> 2, c4 = rem & 3;
            uint32_t dst = sb + s * GST + p * 10240 + row * 80 + c4 * 16;
            uint32_t sz = 16;
            const __nv_bfloat16* src;
            if (p < 2) {
                int gm = bm + row;
                int g  = gm < M ? gm : 0;
                if (gm >= M) sz = 0;
                src = (p == 0 ? Ah : Al) + (size_t)g * K + kb + c4 * 8;
            } else {
                src = (p == 2 ? Bh : Bl) + (size_t)(bn + row) * K + kb + c4 * 8;
            }
            CP_ASYNC16(dst, src, sz);
        }
    };

    issue(0, 0);
    CP_COMMIT();

    int s = 0;
    for (int kb = 0; kb < K; kb += 32, s ^= 1) {
        if (kb + 32 < K) {
            issue(kb + 32, s ^ 1);
            CP_COMMIT();
            CP_WAIT(1);
        } else {
            CP_WAIT(0);
        }
        __syncthreads();

        uint32_t base = sb + s * GST;
        uint32_t aAh = base +     0 + (m0 + ra) * 80 + ca * 16;
        uint32_t aAl = base + 10240 + (m0 + ra) * 80 + ca * 16;
        uint32_t aBh = base + 20480 + (n0 + rb) * 80 + cb * 16;
        uint32_t aBl = base + 30720 + (n0 + rb) * 80 + cb * 16;

#pragma unroll
        for (int ks = 0; ks < 2; ks++) {
            uint32_t ah[2][4], al[2][4], bh[4][4], bl[4][4];
            ldmx4(ah[0], aAh + ks * 32);
            ldmx4(ah[1], aAh + 16 * 80 + ks * 32);
            ldmx4(al[0], aAl + ks * 32);
            ldmx4(al[1], aAl + ks * 32 + 16 * 80);
#pragma unroll
            for (int j = 0; j < 4; j++) {
                ldmx4(bh[j], aBh + j * 16 * 80 + ks * 32);
                ldmx4(bl[j], aBl + j * 16 * 80 + ks * 32);
            }
#pragma unroll
            for (int mi = 0; mi < 2; mi++)
#pragma unroll
                for (int nj = 0; nj < 8; nj++) {
                    const uint32_t* bhp = &bh[nj >> 1][(nj & 1) * 2];
                    const uint32_t* blp = &bl[nj >> 1][(nj & 1) * 2];
                    mma_bf16(c[mi][nj], ah[mi], bhp);
                    mma_bf16(c[mi][nj], al[mi], bhp);
                    mma_bf16(c[mi][nj], ah[mi], blp);
                }
        }
        __syncthreads();
    }

    const int cr = lane >> 2, cc = (lane & 3) * 2;
#pragma unroll
    for (int nj = 0; nj < 8; nj++) {
        int bcol = bn + n0 + nj * 8 + cc;
        float b0 = bias[bcol], b1 = bias[bcol + 1];
#pragma unroll
        for (int mi = 0; mi < 2; mi++) {
#pragma unroll
            for (int hf = 0; hf < 2; hf++) {
                int r = bm + m0 + mi * 16 + cr + hf * 8;
                if (r >= M) continue;
                float o0 = c[mi][nj][hf*2+0] + b0;
                float o1 = c[mi][nj][hf*2+1] + b1;
                if (OUT_SPLIT) {
                    uint32_t h, l;
                    split2(o0, o1, h, l);
                    *(uint32_t*)&CH[(size_t)r * N + bcol] = h;
                    *(uint32_t*)&CL[(size_t)r * N + bcol] = l;
                } else {
                    *(float2*)&C[(size_t)r * N + bcol] = make_float2(o0, o1);
                }
            }
        }
    }
}

__global__ __launch_bounds__(256) void gemm_hmma_kernel(
    const __nv_bfloat16* __restrict__ Ah, const __nv_bfloat16* __restrict__ Al,
    const __nv_bfloat16* __restrict__ Bh, const __nv_bfloat16* __restrict__ Bl,
    const float* __restrict__ bias, float* __restrict__ C, int M, int N, int K)
{
    gemm_body<0>(Ah, Al, Bh, Bl, bias, C, nullptr, nullptr, M, N, K);
}

__global__ __launch_bounds__(256) void gemm_hmma_split_kernel(
    const __nv_bfloat16* __restrict__ Ah, const __nv_bfloat16* __restrict__ Al,
    const __nv_bfloat16* __restrict__ Bh, const __nv_bfloat16* __restrict__ Bl,
    const float* __restrict__ bias,
    __nv_bfloat16* __restrict__ CH, __nv_bfloat16* __restrict__ CL, int M, int N, int K)
{
    gemm_body<1>(Ah, Al, Bh, Bl, bias, nullptr, CH, CL, M, N, K);
}

// ============================================================
// Stage 1 (HMMA): per (b,h,f, 128-query tile) fused attention.
// ============================================================
#define S1_OPH   0
#define S1_OPL   59392
#define S1_OQH   0
#define S1_OQL   18432
#define S1_OKH   36864
#define S1_OKL   69120
#define S1_OVH   118784
#define S1_OVL   151040
#define S1_ORMAX 183296
#define S1_ORSUM 184320
#define S1_SMEM  185344

__global__ __launch_bounds__(256) void stage1_mma_kernel(
    const __nv_bfloat16* __restrict__ Qh_, const __nv_bfloat16* __restrict__ Ql_,
    const __nv_bfloat16* __restrict__ Kh_, const __nv_bfloat16* __restrict__ Kl_,
    const __nv_bfloat16* __restrict__ Vh_, const __nv_bfloat16* __restrict__ Vl_,
    __nv_bfloat16* __restrict__ XH, __nv_bfloat16* __restrict__ XL,
    float* __restrict__ SA)
{
    extern __shared__ char sm[];
    const uint32_t sb = smem_u32(sm);
    const int tid = threadIdx.x;
    const int wid = tid >> 5, lane = tid & 31;
    const int wm = wid & 3, wn = wid >> 2;
    const int q0g = blockIdx.x * 128;
    const int f   = blockIdx.y;
    const int bh  = blockIdx.z;
    const int b   = bh / Hh, h = bh % Hh;

    // ---- load Q planes: 2 planes x 128 rows x 8 chunks ----
    for (int t = tid; t < 2048; t += 256) {
        int p = t >> 10, r = (t >> 3) & 127, ch = t & 7;
        int qg = q0g + r;
        uint4 v = make_uint4(0,0,0,0);
        if (qg < Ss) {
            const __nv_bfloat16* src = (p ? Ql_ : Qh_) + (size_t)(b*Ss + qg)*Dd + h*64 + ch*8;
            v = *(const uint4*)src;
        }
        *(uint4*)(sm + (p ? S1_OQL : S1_OQH) + r*144 + ch*16) = v;
    }
    // ---- load K planes: 2 planes x 224 rows x 8 chunks (FIXED decode) ----
    for (int t = tid; t < 3584; t += 256) {
        int p = t / 1792, rem = t % 1792;
        int kk = rem >> 3, ch = rem & 7;
        uint4 v = make_uint4(0,0,0,0);
        if (kk < NSP) {
            const __nv_bfloat16* src = (p ? Kl_ : Kh_) + (size_t)(b*Ss + f*NSP + kk)*Dd + h*64 + ch*8;
            v = *(const uint4*)src;
        }
        *(uint4*)(sm + (p ? S1_OKL : S1_OKH) + kk*144 + ch*16) = v;
    }
    // ---- load V planes: 2 planes x 224 rows x 8 chunks (FIXED decode) ----
    for (int t = tid; t < 3584; t += 256) {
        int p = t / 1792, rem = t % 1792;
        int kk = rem >> 3, ch = rem & 7;
        uint4 v = make_uint4(0,0,0,0);
        if (kk < NSP) {
            const __nv_bfloat16* src = (p ? Vl_ : Vh_) + (size_t)(b*Ss + f*NSP + kk)*Dd + h*64 + ch*8;
            v = *(const uint4*)src;
        }
        *(uint4*)(sm + (p ? S1_OVL : S1_OVH) + kk*144 + ch*16) = v;
    }
    __syncthreads();

    const int ra = (lane & 7) + ((lane >> 3) & 1) * 8;
    const int ca = (lane >> 4) & 1;
    const int rb = (lane & 7) + ((lane >> 4) & 1) * 8;
    const int cb = (lane >> 3) & 1;

    // ---- QK^T: C[128][208] ; warp tile 32 x 104 ----
    float c[2][13][4];
#pragma unroll
    for (int i = 0; i < 2; i++)
#pragma unroll
        for (int j = 0; j < 13; j++)
#pragma unroll
            for (int e = 0; e < 4; e++) c[i][j][e] = 0.f;

    {
        uint32_t aQh = sb + S1_OQH + (wm*32 + ra)*144 + ca*16;
        uint32_t aQl = sb + S1_OQL + (wm*32 + ra)*144 + ca*16;
        uint32_t aKh = sb + S1_OKH + (wn*104 + rb)*144 + cb*16;
        uint32_t aKl = sb + S1_OKL + (wn*104 + rb)*144 + cb*16;
#pragma unroll
        for (int ks = 0; ks < 4; ks++) {
            uint32_t ah[2][4], al[2][4], bh_[7][4], bl_[7][4];
            ldmx4(ah[0], aQh + ks*32);
            ldmx4(ah[1], aQh + 16*144 + ks*32);
            ldmx4(al[0], aQl + ks*32);
            ldmx4(al[1], aQl + 16*144 + ks*32);
#pragma unroll
            for (int j = 0; j < 7; j++) {
                ldmx4(bh_[j], aKh + j*16*144 + ks*32);
                ldmx4(bl_[j], aKl + j*16*144 + ks*32);
            }
#pragma unroll
            for (int mi = 0; mi < 2; mi++)
#pragma unroll
                for (int nj = 0; nj < 13; nj++) {
                    const uint32_t* bhp = &bh_[nj >> 1][(nj & 1) * 2];
                    const uint32_t* blp = &bl_[nj >> 1][(nj & 1) * 2];
                    mma_bf16(c[mi][nj], ah[mi], bhp);
                    mma_bf16(c[mi][nj], al[mi], bhp);
                    mma_bf16(c[mi][nj], ah[mi], blp);
                }
        }
    }

    // ---- softmax over 196 cols (fp32) ----
    float* rmax = (float*)(sm + S1_ORMAX);
    float* rsum = (float*)(sm + S1_ORSUM);
    const int qr = lane >> 2, qc = (lane & 3) * 2;

    float mx[2][2] = {{-1e30f,-1e30f},{-1e30f,-1e30f}};
#pragma unroll
    for (int mi = 0; mi < 2; mi++)
#pragma unroll
        for (int nj = 0; nj < 13; nj++) {
            int col = wn*104 + nj*8 + qc;
            if (col < NSP) {
#pragma unroll
                for (int hf = 0; hf < 2; hf++) {
                    mx[mi][hf] = fmaxf(mx[mi][hf], fmaxf(c[mi][nj][hf*2], c[mi][nj][hf*2+1]));
                }
            }
        }
#pragma unroll
    for (int mi = 0; mi < 2; mi++)
#pragma unroll
        for (int hf = 0; hf < 2; hf++) {
            float m = mx[mi][hf];
            m = fmaxf(m, __shfl_xor_sync(0xffffffffu, m, 1));
            m = fmaxf(m, __shfl_xor_sync(0xffffffffu, m, 2));
            mx[mi][hf] = m;
            if ((lane & 3) == 0)
                rmax[wn*128 + wm*32 + mi*16 + qr + hf*8] = m;
        }
    __syncthreads();

    float Mv[2][2], sum_[2][2] = {{0,0},{0,0}};
#pragma unroll
    for (int mi = 0; mi < 2; mi++)
#pragma unroll
        for (int hf = 0; hf < 2; hf++) {
            int row = wm*32 + mi*16 + qr + hf*8;
            Mv[mi][hf] = fmaxf(rmax[row], rmax[128 + row]);
        }
#pragma unroll
    for (int mi = 0; mi < 2; mi++)
#pragma unroll
        for (int nj = 0; nj < 13; nj++) {
            int col = wn*104 + nj*8 + qc;
            bool valid = col < NSP;
#pragma unroll
            for (int hf = 0; hf < 2; hf++) {
                float e0 = valid ? __expf(SCALE*(c[mi][nj][hf*2]   - Mv[mi][hf])) : 0.f;
                float e1 = valid ? __expf(SCALE*(c[mi][nj][hf*2+1] - Mv[mi][hf])) : 0.f;
                c[mi][nj][hf*2]   = e0;
                c[mi][nj][hf*2+1] = e1;
                sum_[mi][hf] += e0 + e1;
            }
        }
#pragma unroll
    for (int mi = 0; mi < 2; mi++)
#pragma unroll
        for (int hf = 0; hf < 2; hf++) {
            float s = sum_[mi][hf];
            s += __shfl_xor_sync(0xffffffffu, s, 1);
            s += __shfl_xor_sync(0xffffffffu, s, 2);
            if ((lane & 3) == 0)
                rsum[wn*128 + wm*32 + mi*16 + qr + hf*8] = s;
        }
    __syncthreads();

    // ---- normalize, store SA (fp32) + P planes (bf16) ----
#pragma unroll
    for (int mi = 0; mi < 2; mi++)
#pragma unroll
        for (int hf = 0; hf < 2; hf++) {
            int row = wm*32 + mi*16 + qr + hf*8;
            int qg  = q0g + row;
            float inv = 1.f / (rsum[row] + rsum[128 + row]);
            bool rowv = qg < Ss;
            float* sap = rowv ? &SA[((size_t)(bh*Ss + qg)*Ff + f)*NSP] : nullptr;
#pragma unroll
            for (int nj = 0; nj < 13; nj++) {
                int col = wn*104 + nj*8 + qc;
                float p0 = c[mi][nj][hf*2]   * inv;
                float p1 = c[mi][nj][hf*2+1] * inv;
                if (rowv && col < NSP)
                    *(float2*)&sap[col] = make_float2(p0, p1);
                uint32_t hb, lb;
                split2(p0, p1, hb, lb);
                *(uint32_t*)(sm + S1_OPH + row*464 + col*2) = hb;
                *(uint32_t*)(sm + S1_OPL + row*464 + col*2) = lb;
            }
        }
    // zero P pad cols 208..231
    for (int t = tid; t < 768; t += 256) {
        int p = t / 384, rem = t % 384;
        int rr = rem / 3, j = rem % 3;
        *(uint4*)(sm + (p ? S1_OPL : S1_OPH) + rr*464 + 416 + j*16) = make_uint4(0,0,0,0);
    }
    __syncthreads();

    // ---- P@V: C2[128][64]; warp tile 32 x 32; contraction 224 ----
    float c2[2][4][4];
#pragma unroll
    for (int i = 0; i < 2; i++)
#pragma unroll
        for (int j = 0; j < 4; j++)
#pragma unroll
            for (int e = 0; e < 4; e++) c2[i][j][e] = 0.f;

    {
        const int rv = (lane & 7) + ((lane >> 3) & 1) * 8;
        const int cv = (lane >> 4) & 1;
        uint32_t aPh = sb + S1_OPH + (wm*32 + ra)*464 + ca*16;
        uint32_t aPl = sb + S1_OPL + (wm*32 + ra)*464 + ca*16;
        uint32_t aVh = sb + S1_OVH + rv*144 + (wn*32)*2 + cv*16;
        uint32_t aVl = sb + S1_OVL + rv*144 + (wn*32)*2 + cv*16;
#pragma unroll
        for (int ks = 0; ks < 14; ks++) {
            uint32_t ph[2][4], pl[2][4], vh[2][4], vl[2][4];
            ldmx4(ph[0], aPh + ks*32);
            ldmx4(ph[1], aPh + 16*464 + ks*32);
            ldmx4(pl[0], aPl + ks*32);
            ldmx4(pl[1], aPl + 16*464 + ks*32);
            ldmx4t(vh[0], aVh + ks*16*144);
            ldmx4t(vh[1], aVh + ks*16*144 + 32);
            ldmx4t(vl[0], aVl + ks*16*144);
            ldmx4t(vl[1], aVl + ks*16*144 + 32);
#pragma unroll
            for (int mi = 0; mi < 2; mi++)
#pragma unroll
                for (int nj = 0; nj < 4; nj++) {
                    const uint32_t* bhp = &vh[nj >> 1][(nj & 1) * 2];
                    const uint32_t* blp = &vl[nj >> 1][(nj & 1) * 2];
                    mma_bf16(c2[mi][nj], ph[mi], bhp);
                    mma_bf16(c2[mi][nj], pl[mi], bhp);
                    mma_bf16(c2[mi][nj], ph[mi], blp);
                }
        }
    }

    // ---- store X planes ----
#pragma unroll
    for (int mi = 0; mi < 2; mi++)
#pragma unroll
        for (int hf = 0; hf < 2; hf++) {
            int row = wm*32 + mi*16 + qr + hf*8;
            int qg  = q0g + row;
            if (qg >= Ss) continue;
            size_t base = ((size_t)(b*Ss + qg)*Ff + f)*Dd + h*64;
#pragma unroll
            for (int nj = 0; nj < 4; nj++) {
                int col = wn*32 + nj*8 + qc;
                uint32_t hb, lb;
                split2(c2[mi][nj][hf*2], c2[mi][nj][hf*2+1], hb, lb);
                *(uint32_t*)&XH[base + col] = hb;
                *(uint32_t*)&XL[base + col] = lb;
            }
        }
}

// ============================================================
// Diagonal gather on bf16 planes
// ============================================================
__global__ void diag_kernel(const uint2* __restrict__ XH, const uint2* __restrict__ XL,
                            uint2* __restrict__ XDH, uint2* __restrict__ XDL)
{
    int idx = blockIdx.x * blockDim.x + threadIdx.x;
    if (idx >= BSD/4) return;
    int c4   = idx % (Dd/4);
    int rest = idx / (Dd/4);
    int s = rest % Ss;
    int b = rest / Ss;
    int f = s / NSP;
    size_t src = ((size_t)(b*Ss + s)*Ff + f)*(Dd/4) + c4;
    XDH[idx] = XH[src];
    XDL[idx] = XL[src];
}

// ============================================================
// Stage 2: trajectory attention over F=8 frames
// ============================================================
__global__ __launch_bounds__(128) void stage2_kernel(
    const float* __restrict__ Q2, const float* __restrict__ KV,
    __nv_bfloat16* __restrict__ T2H, __nv_bfloat16* __restrict__ T2L)
{
    int gw = (blockIdx.x * blockDim.x + threadIdx.x) >> 5;
    if (gw >= BS*Hh) return;
    int h = gw % Hh;
    int s = (gw / Hh) % Ss;
    int b = gw / (Hh*Ss);
    int lane = threadIdx.x & 31;

    const float* q2p = Q2 + (size_t)(b*Ss + s)*Dd + h*64;
    float qa = q2p[lane], qb = q2p[lane+32];

    const float* kvp = KV + (size_t)(b*Ss + s)*Ff*2*Dd;

    float logit[Ff];
#pragma unroll
    for (int f = 0; f < Ff; f++) {
        const float* k2 = kvp + (size_t)f*2*Dd + h*64;
        float p = qa*k2[lane] + qb*k2[lane+32];
#pragma unroll
        for (int o = 16; o > 0; o >>= 1) p += __shfl_xor_sync(0xffffffffu, p, o);
        logit[f] = p * SCALE;
    }
    float m = logit[0];
#pragma unroll
    for (int f = 1; f < Ff; f++) m = fmaxf(m, logit[f]);
    float e[Ff], sum = 0.f;
#pragma unroll
    for (int f = 0; f < Ff; f++) { e[f] = __expf(logit[f]-m); sum += e[f]; }
    float inv = 1.f / sum;
    float oa = 0.f, ob = 0.f;
#pragma unroll
    for (int f = 0; f < Ff; f++) {
        const float* v2 = kvp + (size_t)f*2*Dd + Dd + h*64;
        float w = e[f]*inv;
        oa += w*v2[lane]; ob += w*v2[lane+32];
    }
    size_t off = (size_t)(b*Ss + s)*Dd + h*64;
    __nv_bfloat16 ha = __float2bfloat16(oa);
    __nv_bfloat16 hb = __float2bfloat16(ob);
    T2H[off + lane]      = ha;
    T2H[off + lane + 32] = hb;
    T2L[off + lane]      = __float2bfloat16(oa - __bfloat162float(ha));
    T2L[off + lane + 32] = __float2bfloat16(ob - __bfloat162float(hb));
}

// ============================================================
// launch
// ============================================================
extern "C" void kernel_launch(void* const* d_in, const int* in_sizes, int n_in,
                              void* d_out, int out_size)
{
    const float* query = (const float*)d_in[0];
    const float* key_t = (const float*)d_in[1];
    const float* value = (const float*)d_in[2];
    const float* Wq   = (const float*)d_in[3];
    const float* bq   = (const float*)d_in[4];
    const float* Wk   = (const float*)d_in[5];
    const float* bk   = (const float*)d_in[6];
    const float* Wv   = (const float*)d_in[7];
    const float* bv   = (const float*)d_in[8];
    const float* Wpq  = (const float*)d_in[9];
    const float* bpq  = (const float*)d_in[10];
    const float* Wpkv = (const float*)d_in[11];
    const float* bpkv = (const float*)d_in[12];
    const float* Wp   = (const float*)d_in[13];
    const float* bp   = (const float*)d_in[14];

    float* out = (float*)d_out;            // (B, S, D)
    float* sa  = out + BSD;                // (B*H, S, F, n)

    float *q2, *kv;
    __nv_bfloat16 *wth, *wtl;
    __nv_bfloat16 *inqh, *inql, *inkh, *inkl, *invh, *invl;
    __nv_bfloat16 *qph, *qpl, *kph, *kpl, *vph, *vpl;
    __nv_bfloat16 *xh, *xl, *xdh, *xdl, *t2h, *t2l;
    cudaGetSymbolAddress((void**)&q2,  g_q2);
    cudaGetSymbolAddress((void**)&kv,  g_kv);
    cudaGetSymbolAddress((void**)&wth, g_wth);
    cudaGetSymbolAddress((void**)&wtl, g_wtl);
    cudaGetSymbolAddress((void**)&inqh, g_inqh);
    cudaGetSymbolAddress((void**)&inql, g_inql);
    cudaGetSymbolAddress((void**)&inkh, g_inkh);
    cudaGetSymbolAddress((void**)&inkl, g_inkl);
    cudaGetSymbolAddress((void**)&invh, g_invh);
    cudaGetSymbolAddress((void**)&invl, g_invl);
    cudaGetSymbolAddress((void**)&qph, g_qph);
    cudaGetSymbolAddress((void**)&qpl, g_qpl);
    cudaGetSymbolAddress((void**)&kph, g_kph);
    cudaGetSymbolAddress((void**)&kpl, g_kpl);
    cudaGetSymbolAddress((void**)&vph, g_vph);
    cudaGetSymbolAddress((void**)&vpl, g_vpl);
    cudaGetSymbolAddress((void**)&xh,  g_xh);
    cudaGetSymbolAddress((void**)&xl,  g_xl);
    cudaGetSymbolAddress((void**)&xdh, g_xdh);
    cudaGetSymbolAddress((void**)&xdl, g_xdl);
    cudaGetSymbolAddress((void**)&t2h, g_t2h);
    cudaGetSymbolAddress((void**)&t2l, g_t2l);

    cudaFuncSetAttribute(stage1_mma_kernel,
                         cudaFuncAttributeMaxDynamicSharedMemorySize, S1_SMEM);
    cudaFuncSetAttribute(gemm_hmma_kernel,
                         cudaFuncAttributeMaxDynamicSharedMemorySize, G_SMEM_BYTES);
    cudaFuncSetAttribute(gemm_hmma_split_kernel,
                         cudaFuncAttributeMaxDynamicSharedMemorySize, G_SMEM_BYTES);

    // ---- weight transpose + split ----
    dim3 wb(32, 8);
    wtrans_kernel<<<dim3(24,24), wb>>>(Wq,   wth+OFF_WQ,   wtl+OFF_WQ,   768, 768);
    wtrans_kernel<<<dim3(24,24), wb>>>(Wk,   wth+OFF_WK,   wtl+OFF_WK,   768, 768);
    wtrans_kernel<<<dim3(24,24), wb>>>(Wv,   wth+OFF_WV,   wtl+OFF_WV,   768, 768);
    wtrans_kernel<<<dim3(24,24), wb>>>(Wpq,  wth+OFF_WPQ,  wtl+OFF_WPQ,  768, 768);
    wtrans_kernel<<<dim3(24,24), wb>>>(Wp,   wth+OFF_WP,   wtl+OFF_WP,   768, 768);
    wtrans_kernel<<<dim3(48,24), wb>>>(Wpkv, wth+OFF_WPKV, wtl+OFF_WPKV, 768, 1536);

    // ---- split fp32 inputs to bf16 planes ----
    int n4 = BSD/4, sg = (n4 + 255)/256;
    split_kernel<<<sg, 256>>>((const float4*)query, (uint2*)inqh, (uint2*)inql, n4);
    split_kernel<<<sg, 256>>>((const float4*)key_t, (uint2*)inkh, (uint2*)inkl, n4);
    split_kernel<<<sg, 256>>>((const float4*)value, (uint2*)invh, (uint2*)invl, n4);

    dim3 gP(6, 25);       // N=768, M=3136
    dim3 gKV(12, 196);    // N=1536, M=25088

    // projections -> bf16 hi/lo planes directly
    gemm_hmma_split_kernel<<<gP, 256, G_SMEM_BYTES>>>(inqh, inql, wth+OFF_WQ, wtl+OFF_WQ, bq, qph, qpl, BS, 768, 768);
    gemm_hmma_split_kernel<<<gP, 256, G_SMEM_BYTES>>>(inkh, inkl, wth+OFF_WK, wtl+OFF_WK, bk, kph, kpl, BS, 768, 768);
    gemm_hmma_split_kernel<<<gP, 256, G_SMEM_BYTES>>>(invh, invl, wth+OFF_WV, wtl+OFF_WV, bv, vph, vpl, BS, 768, 768);

    stage1_mma_kernel<<<dim3(13, Ff, Bb*Hh), 256, S1_SMEM>>>(
        qph, qpl, kph, kpl, vph, vpl, xh, xl, sa);

    diag_kernel<<<(BSD/4 + 255)/256, 256>>>(
        (const uint2*)xh, (const uint2*)xl, (uint2*)xdh, (uint2*)xdl);

    gemm_hmma_kernel<<<gP, 256, G_SMEM_BYTES>>>(xdh, xdl, wth+OFF_WPQ, wtl+OFF_WPQ, bpq, q2, BS, 768, 768);
    gemm_hmma_kernel<<<gKV, 256, G_SMEM_BYTES>>>(xh, xl, wth+OFF_WPKV, wtl+OFF_WPKV, bpkv, kv, BS*Ff, 1536, 768);

    stage2_kernel<<<(BS*Hh)/4, 128>>>(q2, kv, t2h, t2l);

    gemm_hmma_kernel<<<gP, 256, G_SMEM_BYTES>>>(t2h, t2l, wth+OFF_WP, wtl+OFF_WP, bp, out, BS, 768, 768);
}

// round 7
// speedup vs baseline: 3.4338x; 1.3509x over previous
#include <cuda_runtime.h>
#include <cuda_bf16.h>
#include <cstdint>
#include <cstddef>

// ---- problem constants ----
#define Bb   2
#define Ss   1568
#define Dd   768
#define Hh   12
#define HDd  64
#define Ff   8
#define NSP  196
#define BS   (Bb*Ss)             // 3136
#define BSD  (Bb*Ss*Dd)          // 2408448
#define XSZ  (Bb*Ss*Ff*Dd)       // 19267584
#define SCALE 0.125f

// ---- scratch ----
__device__ float g_m[(size_t)BS*Hh*Dd];      // [t][h][768] fp32 logit-matrices
__device__ float g_zerob[768];               // zero bias (static-zeroed)

// bf16 hi/lo planes
__device__ __align__(16) __nv_bfloat16 g_inqh[BSD], g_inql[BSD];
__device__ __align__(16) __nv_bfloat16 g_inkh[BSD], g_inkl[BSD];
__device__ __align__(16) __nv_bfloat16 g_invh[BSD], g_invl[BSD];
__device__ __align__(16) __nv_bfloat16 g_qph[BSD], g_qpl[BSD];
__device__ __align__(16) __nv_bfloat16 g_kph[BSD], g_kpl[BSD];
__device__ __align__(16) __nv_bfloat16 g_vph[BSD], g_vpl[BSD];
__device__ __align__(16) __nv_bfloat16 g_xh [XSZ], g_xl [XSZ];
__device__ __align__(16) __nv_bfloat16 g_xdh[BSD], g_xdl[BSD];
__device__ __align__(16) __nv_bfloat16 g_q2h[BSD], g_q2l[BSD];
__device__ __align__(16) __nv_bfloat16 g_xwh[(size_t)BS*Hh*Dd], g_xwl[(size_t)BS*Hh*Dd];
__device__ __align__(16) __nv_bfloat16 g_t2h[BSD], g_t2l[BSD];
__device__ __align__(16) __nv_bfloat16 g_wk2h[768*768], g_wk2l[768*768]; // Wpkv[:, :768] row-major split

// transposed+split weights: [N][K] bf16, hi and lo parts
#define WSQ  (768*768)
#define OFF_WQ   0
#define OFF_WK   (1*WSQ)
#define OFF_WV   (2*WSQ)
#define OFF_WPQ  (3*WSQ)
#define OFF_WP   (4*WSQ)
#define OFF_WPKV (5*WSQ)
#define WT_ELEMS (5*WSQ + 1536*768)
__device__ __align__(16) __nv_bfloat16 g_wth[WT_ELEMS];
__device__ __align__(16) __nv_bfloat16 g_wtl[WT_ELEMS];

// ============================================================
// helpers
// ============================================================
__device__ __forceinline__ uint32_t smem_u32(const void* p) {
    uint32_t a;
    asm("{ .reg .u64 t; cvta.to.shared.u64 t, %1; cvt.u32.u64 %0, t; }" : "=r"(a) : "l"(p));
    return a;
}
__device__ __forceinline__ void ldmx4(uint32_t* r, uint32_t a) {
    asm volatile("ldmatrix.sync.aligned.m8n8.x4.shared.b16 {%0,%1,%2,%3}, [%4];"
        : "=r"(r[0]), "=r"(r[1]), "=r"(r[2]), "=r"(r[3]) : "r"(a));
}
__device__ __forceinline__ void ldmx4t(uint32_t* r, uint32_t a) {
    asm volatile("ldmatrix.sync.aligned.m8n8.x4.trans.shared.b16 {%0,%1,%2,%3}, [%4];"
        : "=r"(r[0]), "=r"(r[1]), "=r"(r[2]), "=r"(r[3]) : "r"(a));
}
__device__ __forceinline__ void mma_bf16(float* c, const uint32_t* a, const uint32_t* b) {
    asm volatile("mma.sync.aligned.m16n8k16.row.col.f32.bf16.bf16.f32 "
        "{%0,%1,%2,%3}, {%4,%5,%6,%7}, {%8,%9}, {%0,%1,%2,%3};"
        : "+f"(c[0]), "+f"(c[1]), "+f"(c[2]), "+f"(c[3])
        : "r"(a[0]), "r"(a[1]), "r"(a[2]), "r"(a[3]), "r"(b[0]), "r"(b[1]));
}
#define CP_ASYNC16(dst, src, sz) \
    asm volatile("cp.async.cg.shared.global [%0], [%1], 16, %2;" \
                 :: "r"(dst), "l"(src), "r"(sz))
#define CP_COMMIT() asm volatile("cp.async.commit_group;" ::: "memory")
#define CP_WAIT(n)  asm volatile("cp.async.wait_group %0;" :: "n"(n) : "memory")

__device__ __forceinline__ void split2(float a, float b, uint32_t& h, uint32_t& l) {
    __nv_bfloat162 hh = __floats2bfloat162_rn(a, b);
    float2 f = __bfloat1622float2(hh);
    __nv_bfloat162 ll = __floats2bfloat162_rn(a - f.x, b - f.y);
    h = *(uint32_t*)&hh; l = *(uint32_t*)&ll;
}

// ============================================================
// Weight transpose + bf16 split: W[K][N] fp32 -> hi/lo [N][K] bf16
// ============================================================
__global__ void wtrans_kernel(const float* __restrict__ W,
                              __nv_bfloat16* __restrict__ hi,
                              __nv_bfloat16* __restrict__ lo, int K, int N)
{
    __shared__ float t[32][33];
    int n0 = blockIdx.x * 32, k0 = blockIdx.y * 32;
    int tx = threadIdx.x, ty = threadIdx.y;
#pragma unroll
    for (int i = 0; i < 32; i += 8)
        t[ty + i][tx] = W[(size_t)(k0 + ty + i) * N + n0 + tx];
    __syncthreads();
#pragma unroll
    for (int i = 0; i < 32; i += 8) {
        float v = t[tx][ty + i];
        __nv_bfloat16 h = __float2bfloat16(v);
        __nv_bfloat16 l = __float2bfloat16(v - __bfloat162float(h));
        size_t o = (size_t)(n0 + ty + i) * K + k0 + tx;
        hi[o] = h; lo[o] = l;
    }
}

// ============================================================
// elementwise fp32 -> bf16 hi/lo planes
// ============================================================
__global__ void split_kernel(const float4* __restrict__ in,
                             uint2* __restrict__ H, uint2* __restrict__ L, int n4)
{
    int i = blockIdx.x * blockDim.x + threadIdx.x;
    if (i >= n4) return;
    float4 a = in[i];
    uint32_t h01, l01, h23, l23;
    split2(a.x, a.y, h01, l01);
    split2(a.z, a.w, h23, l23);
    H[i] = make_uint2(h01, h23);
    L[i] = make_uint2(l01, l23);
}

// split Wpkv[:, :768] row-major (no transpose): wk2[j][c] = Wpkv[j][c]
__global__ void splitwk2_kernel(const float* __restrict__ Wpkv,
                                __nv_bfloat16* __restrict__ H, __nv_bfloat16* __restrict__ L)
{
    int i = blockIdx.x * blockDim.x + threadIdx.x;   // over 768*192 float4s
    if (i >= 768*192) return;
    int j = i / 192, c4 = (i % 192) * 4;
    float4 a = *(const float4*)&Wpkv[(size_t)j * 1536 + c4];
    uint32_t h01, l01, h23, l23;
    split2(a.x, a.y, h01, l01);
    split2(a.z, a.w, h23, l23);
    *(uint2*)&H[(size_t)j*768 + c4] = make_uint2(h01, h23);
    *(uint2*)&L[(size_t)j*768 + c4] = make_uint2(l01, l23);
}

// ============================================================
// HMMA bf16x3 GEMM, templated: NTILE in {128, 64}, OUT_SPLIT in {0,1}
// A[M][K] via lda; B[N][K] via ldb; C via ldc. 128xNTILE tile, BK=32.
// ============================================================
template <int OUT_SPLIT, int NTILE>
__device__ __forceinline__ void gemm_body(
    const __nv_bfloat16* __restrict__ Ah, const __nv_bfloat16* __restrict__ Al, int lda,
    const __nv_bfloat16* __restrict__ Bh, const __nv_bfloat16* __restrict__ Bl, int ldb,
    const float* __restrict__ bias,
    float* __restrict__ C, __nv_bfloat16* __restrict__ CH, __nv_bfloat16* __restrict__ CL,
    int ldc, int M, int K)
{
    constexpr int NJ  = NTILE / 16;        // mma n-tiles per warp
    constexpr int BST = NTILE * 80;        // bytes per B plane
    constexpr int STG = 20480 + 2 * BST;   // bytes per stage
    constexpr int CPN = 1024 + NTILE * 8;  // cp.async ops per stage

    extern __shared__ char smem[];
    const uint32_t sb = smem_u32(smem);
    const int tid = threadIdx.x;
    const int wid = tid >> 5, lane = tid & 31;
    const int bm = blockIdx.y * 128, bn = blockIdx.x * NTILE;
    const int m0 = (wid & 3) * 32;
    const int n0 = (wid >> 2) * (NTILE / 2);

    float c[2][NJ][4];
#pragma unroll
    for (int i = 0; i < 2; i++)
#pragma unroll
        for (int j = 0; j < NJ; j++)
#pragma unroll
            for (int e = 0; e < 4; e++) c[i][j][e] = 0.f;

    const int ra = (lane & 7) + ((lane >> 3) & 1) * 8;
    const int ca = (lane >> 4) & 1;
    const int rb = (lane & 7) + ((lane >> 4) & 1) * 8;
    const int cb = (lane >> 3) & 1;

    auto issue = [&](int kb, int s) {
        for (int i = tid; i < CPN; i += 256) {
            uint32_t dst, sz = 16;
            const __nv_bfloat16* src;
            if (i < 1024) {
                int p = i >> 9, rem = i & 511;
                int row = rem >> 2, c4 = rem & 3;
                dst = sb + s * STG + p * 10240 + row * 80 + c4 * 16;
                int gm = bm + row;
                int g  = gm < M ? gm : 0;
                if (gm >= M) sz = 0;
                src = (p == 0 ? Ah : Al) + (size_t)g * lda + kb + c4 * 8;
            } else {
                int i2 = i - 1024;
                int p = i2 / (NTILE * 4), rem = i2 % (NTILE * 4);
                int row = rem >> 2, c4 = rem & 3;
                dst = sb + s * STG + 20480 + p * BST + row * 80 + c4 * 16;
                src = (p == 0 ? Bh : Bl) + (size_t)(bn + row) * ldb + kb + c4 * 8;
            }
            CP_ASYNC16(dst, src, sz);
        }
    };

    issue(0, 0);
    CP_COMMIT();

    int s = 0;
    for (int kb = 0; kb < K; kb += 32, s ^= 1) {
        if (kb + 32 < K) {
            issue(kb + 32, s ^ 1);
            CP_COMMIT();
            CP_WAIT(1);
        } else {
            CP_WAIT(0);
        }
        __syncthreads();

        uint32_t base = sb + s * STG;
        uint32_t aAh = base +     0 + (m0 + ra) * 80 + ca * 16;
        uint32_t aAl = base + 10240 + (m0 + ra) * 80 + ca * 16;
        uint32_t aBh = base + 20480 +       (n0 + rb) * 80 + cb * 16;
        uint32_t aBl = base + 20480 + BST + (n0 + rb) * 80 + cb * 16;

#pragma unroll
        for (int ks = 0; ks < 2; ks++) {
            uint32_t ah[2][4], al[2][4], bh[NJ/2][4], bl[NJ/2][4];
            ldmx4(ah[0], aAh + ks * 32);
            ldmx4(ah[1], aAh + 16 * 80 + ks * 32);
            ldmx4(al[0], aAl + ks * 32);
            ldmx4(al[1], aAl + 16 * 80 + ks * 32);
#pragma unroll
            for (int j = 0; j < NJ/2; j++) {
                ldmx4(bh[j], aBh + j * 16 * 80 + ks * 32);
                ldmx4(bl[j], aBl + j * 16 * 80 + ks * 32);
            }
#pragma unroll
            for (int mi = 0; mi < 2; mi++)
#pragma unroll
                for (int nj = 0; nj < NJ; nj++) {
                    const uint32_t* bhp = &bh[nj >> 1][(nj & 1) * 2];
                    const uint32_t* blp = &bl[nj >> 1][(nj & 1) * 2];
                    mma_bf16(c[mi][nj], ah[mi], bhp);
                    mma_bf16(c[mi][nj], al[mi], bhp);
                    mma_bf16(c[mi][nj], ah[mi], blp);
                }
        }
        __syncthreads();
    }

    const int cr = lane >> 2, cc = (lane & 3) * 2;
#pragma unroll
    for (int nj = 0; nj < NJ; nj++) {
        int colr = n0 + nj * 8 + cc;       // col within tile
        int bcol = bn + colr;              // global col
        float b0 = bias[bcol], b1 = bias[bcol + 1];
#pragma unroll
        for (int mi = 0; mi < 2; mi++) {
#pragma unroll
            for (int hf = 0; hf < 2; hf++) {
                int r = bm + m0 + mi * 16 + cr + hf * 8;
                if (r >= M) continue;
                float o0 = c[mi][nj][hf*2+0] + b0;
                float o1 = c[mi][nj][hf*2+1] + b1;
                if (OUT_SPLIT) {
                    uint32_t h, l;
                    split2(o0, o1, h, l);
                    *(uint32_t*)&CH[(size_t)r * ldc + bcol] = h;
                    *(uint32_t*)&CL[(size_t)r * ldc + bcol] = l;
                } else {
                    *(float2*)&C[(size_t)r * ldc + bcol] = make_float2(o0, o1);
                }
            }
        }
    }
}

template <int OUT_SPLIT, int NTILE>
__global__ __launch_bounds__(256) void gemm_tpl(
    const __nv_bfloat16* Ah, const __nv_bfloat16* Al, int lda, long aZ,
    const __nv_bfloat16* Bh, const __nv_bfloat16* Bl, int ldb, long bZ,
    const float* bias, long biasZ,
    float* C, __nv_bfloat16* CH, __nv_bfloat16* CL, int ldc, long cZ,
    int M, int K)
{
    long z = blockIdx.z;
    gemm_body<OUT_SPLIT, NTILE>(
        Ah + z*aZ, Al + z*aZ, lda,
        Bh + z*bZ, Bl + z*bZ, ldb,
        bias + z*biasZ,
        C  ? C  + z*cZ : nullptr,
        CH ? CH + z*cZ : nullptr,
        CL ? CL + z*cZ : nullptr,
        ldc, M, K);
}

#define SMEM_128 81920
#define SMEM_64  61440

// ============================================================
// Stage 1 (HMMA): per (b,h,f, 128-query tile) fused attention.
// ============================================================
#define S1_OPH   0
#define S1_OPL   59392
#define S1_OQH   0
#define S1_OQL   18432
#define S1_OKH   36864
#define S1_OKL   69120
#define S1_OVH   118784
#define S1_OVL   151040
#define S1_ORMAX 183296
#define S1_ORSUM 184320
#define S1_SMEM  185344

__global__ __launch_bounds__(256) void stage1_mma_kernel(
    const __nv_bfloat16* __restrict__ Qh_, const __nv_bfloat16* __restrict__ Ql_,
    const __nv_bfloat16* __restrict__ Kh_, const __nv_bfloat16* __restrict__ Kl_,
    const __nv_bfloat16* __restrict__ Vh_, const __nv_bfloat16* __restrict__ Vl_,
    __nv_bfloat16* __restrict__ XH, __nv_bfloat16* __restrict__ XL,
    float* __restrict__ SA)
{
    extern __shared__ char sm[];
    const uint32_t sb = smem_u32(sm);
    const int tid = threadIdx.x;
    const int wid = tid >> 5, lane = tid & 31;
    const int wm = wid & 3, wn = wid >> 2;
    const int q0g = blockIdx.x * 128;
    const int f   = blockIdx.y;
    const int bh  = blockIdx.z;
    const int b   = bh / Hh, h = bh % Hh;

    for (int t = tid; t < 2048; t += 256) {
        int p = t >> 10, r = (t >> 3) & 127, ch = t & 7;
        int qg = q0g + r;
        uint4 v = make_uint4(0,0,0,0);
        if (qg < Ss) {
            const __nv_bfloat16* src = (p ? Ql_ : Qh_) + (size_t)(b*Ss + qg)*Dd + h*64 + ch*8;
            v = *(const uint4*)src;
        }
        *(uint4*)(sm + (p ? S1_OQL : S1_OQH) + r*144 + ch*16) = v;
    }
    for (int t = tid; t < 3584; t += 256) {
        int p = t / 1792, rem = t % 1792;
        int kk = rem >> 3, ch = rem & 7;
        uint4 v = make_uint4(0,0,0,0);
        if (kk < NSP) {
            const __nv_bfloat16* src = (p ? Kl_ : Kh_) + (size_t)(b*Ss + f*NSP + kk)*Dd + h*64 + ch*8;
            v = *(const uint4*)src;
        }
        *(uint4*)(sm + (p ? S1_OKL : S1_OKH) + kk*144 + ch*16) = v;
    }
    for (int t = tid; t < 3584; t += 256) {
        int p = t / 1792, rem = t % 1792;
        int kk = rem >> 3, ch = rem & 7;
        uint4 v = make_uint4(0,0,0,0);
        if (kk < NSP) {
            const __nv_bfloat16* src = (p ? Vl_ : Vh_) + (size_t)(b*Ss + f*NSP + kk)*Dd + h*64 + ch*8;
            v = *(const uint4*)src;
        }
        *(uint4*)(sm + (p ? S1_OVL : S1_OVH) + kk*144 + ch*16) = v;
    }
    __syncthreads();

    const int ra = (lane & 7) + ((lane >> 3) & 1) * 8;
    const int ca = (lane >> 4) & 1;
    const int rb = (lane & 7) + ((lane >> 4) & 1) * 8;
    const int cb = (lane >> 3) & 1;

    float c[2][13][4];
#pragma unroll
    for (int i = 0; i < 2; i++)
#pragma unroll
        for (int j = 0; j < 13; j++)
#pragma unroll
            for (int e = 0; e < 4; e++) c[i][j][e] = 0.f;

    {
        uint32_t aQh = sb + S1_OQH + (wm*32 + ra)*144 + ca*16;
        uint32_t aQl = sb + S1_OQL + (wm*32 + ra)*144 + ca*16;
        uint32_t aKh = sb + S1_OKH + (wn*104 + rb)*144 + cb*16;
        uint32_t aKl = sb + S1_OKL + (wn*104 + rb)*144 + cb*16;
#pragma unroll
        for (int ks = 0; ks < 4; ks++) {
            uint32_t ah[2][4], al[2][4], bh_[7][4], bl_[7][4];
            ldmx4(ah[0], aQh + ks*32);
            ldmx4(ah[1], aQh + 16*144 + ks*32);
            ldmx4(al[0], aQl + ks*32);
            ldmx4(al[1], aQl + 16*144 + ks*32);
#pragma unroll
            for (int j = 0; j < 7; j++) {
                ldmx4(bh_[j], aKh + j*16*144 + ks*32);
                ldmx4(bl_[j], aKl + j*16*144 + ks*32);
            }
#pragma unroll
            for (int mi = 0; mi < 2; mi++)
#pragma unroll
                for (int nj = 0; nj < 13; nj++) {
                    const uint32_t* bhp = &bh_[nj >> 1][(nj & 1) * 2];
                    const uint32_t* blp = &bl_[nj >> 1][(nj & 1) * 2];
                    mma_bf16(c[mi][nj], ah[mi], bhp);
                    mma_bf16(c[mi][nj], al[mi], bhp);
                    mma_bf16(c[mi][nj], ah[mi], blp);
                }
        }
    }

    float* rmax = (float*)(sm + S1_ORMAX);
    float* rsum = (float*)(sm + S1_ORSUM);
    const int qr = lane >> 2, qc = (lane & 3) * 2;

    float mx[2][2] = {{-1e30f,-1e30f},{-1e30f,-1e30f}};
#pragma unroll
    for (int mi = 0; mi < 2; mi++)
#pragma unroll
        for (int nj = 0; nj < 13; nj++) {
            int col = wn*104 + nj*8 + qc;
            if (col < NSP) {
#pragma unroll
                for (int hf = 0; hf < 2; hf++)
                    mx[mi][hf] = fmaxf(mx[mi][hf], fmaxf(c[mi][nj][hf*2], c[mi][nj][hf*2+1]));
            }
        }
#pragma unroll
    for (int mi = 0; mi < 2; mi++)
#pragma unroll
        for (int hf = 0; hf < 2; hf++) {
            float m = mx[mi][hf];
            m = fmaxf(m, __shfl_xor_sync(0xffffffffu, m, 1));
            m = fmaxf(m, __shfl_xor_sync(0xffffffffu, m, 2));
            if ((lane & 3) == 0)
                rmax[wn*128 + wm*32 + mi*16 + qr + hf*8] = m;
        }
    __syncthreads();

    float Mv[2][2], sum_[2][2] = {{0,0},{0,0}};
#pragma unroll
    for (int mi = 0; mi < 2; mi++)
#pragma unroll
        for (int hf = 0; hf < 2; hf++) {
            int row = wm*32 + mi*16 + qr + hf*8;
            Mv[mi][hf] = fmaxf(rmax[row], rmax[128 + row]);
        }
#pragma unroll
    for (int mi = 0; mi < 2; mi++)
#pragma unroll
        for (int nj = 0; nj < 13; nj++) {
            int col = wn*104 + nj*8 + qc;
            bool valid = col < NSP;
#pragma unroll
            for (int hf = 0; hf < 2; hf++) {
                float e0 = valid ? __expf(SCALE*(c[mi][nj][hf*2]   - Mv[mi][hf])) : 0.f;
                float e1 = valid ? __expf(SCALE*(c[mi][nj][hf*2+1] - Mv[mi][hf])) : 0.f;
                c[mi][nj][hf*2]   = e0;
                c[mi][nj][hf*2+1] = e1;
                sum_[mi][hf] += e0 + e1;
            }
        }
#pragma unroll
    for (int mi = 0; mi < 2; mi++)
#pragma unroll
        for (int hf = 0; hf < 2; hf++) {
            float s = sum_[mi][hf];
            s += __shfl_xor_sync(0xffffffffu, s, 1);
            s += __shfl_xor_sync(0xffffffffu, s, 2);
            if ((lane & 3) == 0)
                rsum[wn*128 + wm*32 + mi*16 + qr + hf*8] = s;
        }
    __syncthreads();

#pragma unroll
    for (int mi = 0; mi < 2; mi++)
#pragma unroll
        for (int hf = 0; hf < 2; hf++) {
            int row = wm*32 + mi*16 + qr + hf*8;
            int qg  = q0g + row;
            float inv = 1.f / (rsum[row] + rsum[128 + row]);
            bool rowv = qg < Ss;
            float* sap = rowv ? &SA[((size_t)(bh*Ss + qg)*Ff + f)*NSP] : nullptr;
#pragma unroll
            for (int nj = 0; nj < 13; nj++) {
                int col = wn*104 + nj*8 + qc;
                float p0 = c[mi][nj][hf*2]   * inv;
                float p1 = c[mi][nj][hf*2+1] * inv;
                if (rowv && col < NSP)
                    *(float2*)&sap[col] = make_float2(p0, p1);
                uint32_t hb, lb;
                split2(p0, p1, hb, lb);
                *(uint32_t*)(sm + S1_OPH + row*464 + col*2) = hb;
                *(uint32_t*)(sm + S1_OPL + row*464 + col*2) = lb;
            }
        }
    for (int t = tid; t < 768; t += 256) {
        int p = t / 384, rem = t % 384;
        int rr = rem / 3, j = rem % 3;
        *(uint4*)(sm + (p ? S1_OPL : S1_OPH) + rr*464 + 416 + j*16) = make_uint4(0,0,0,0);
    }
    __syncthreads();

    float c2[2][4][4];
#pragma unroll
    for (int i = 0; i < 2; i++)
#pragma unroll
        for (int j = 0; j < 4; j++)
#pragma unroll
            for (int e = 0; e < 4; e++) c2[i][j][e] = 0.f;

    {
        const int rv = (lane & 7) + ((lane >> 3) & 1) * 8;
        const int cv = (lane >> 4) & 1;
        uint32_t aPh = sb + S1_OPH + (wm*32 + ra)*464 + ca*16;
        uint32_t aPl = sb + S1_OPL + (wm*32 + ra)*464 + ca*16;
        uint32_t aVh = sb + S1_OVH + rv*144 + (wn*32)*2 + cv*16;
        uint32_t aVl = sb + S1_OVL + rv*144 + (wn*32)*2 + cv*16;
#pragma unroll
        for (int ks = 0; ks < 14; ks++) {
            uint32_t ph[2][4], pl[2][4], vh[2][4], vl[2][4];
            ldmx4(ph[0], aPh + ks*32);
            ldmx4(ph[1], aPh + 16*464 + ks*32);
            ldmx4(pl[0], aPl + ks*32);
            ldmx4(pl[1], aPl + 16*464 + ks*32);
            ldmx4t(vh[0], aVh + ks*16*144);
            ldmx4t(vh[1], aVh + ks*16*144 + 32);
            ldmx4t(vl[0], aVl + ks*16*144);
            ldmx4t(vl[1], aVl + ks*16*144 + 32);
#pragma unroll
            for (int mi = 0; mi < 2; mi++)
#pragma unroll
                for (int nj = 0; nj < 4; nj++) {
                    const uint32_t* bhp = &vh[nj >> 1][(nj & 1) * 2];
                    const uint32_t* blp = &vl[nj >> 1][(nj & 1) * 2];
                    mma_bf16(c2[mi][nj], ph[mi], bhp);
                    mma_bf16(c2[mi][nj], pl[mi], bhp);
                    mma_bf16(c2[mi][nj], ph[mi], blp);
                }
        }
    }

#pragma unroll
    for (int mi = 0; mi < 2; mi++)
#pragma unroll
        for (int hf = 0; hf < 2; hf++) {
            int row = wm*32 + mi*16 + qr + hf*8;
            int qg  = q0g + row;
            if (qg >= Ss) continue;
            size_t base = ((size_t)(b*Ss + qg)*Ff + f)*Dd + h*64;
#pragma unroll
            for (int nj = 0; nj < 4; nj++) {
                int col = wn*32 + nj*8 + qc;
                uint32_t hb, lb;
                split2(c2[mi][nj][hf*2], c2[mi][nj][hf*2+1], hb, lb);
                *(uint32_t*)&XH[base + col] = hb;
                *(uint32_t*)&XL[base + col] = lb;
            }
        }
}

// ============================================================
// Diagonal gather on bf16 planes
// ============================================================
__global__ void diag_kernel(const uint2* __restrict__ XH, const uint2* __restrict__ XL,
                            uint2* __restrict__ XDH, uint2* __restrict__ XDL)
{
    int idx = blockIdx.x * blockDim.x + threadIdx.x;
    if (idx >= BSD/4) return;
    int c4   = idx % (Dd/4);
    int rest = idx / (Dd/4);
    int s = rest % Ss;
    int b = rest / Ss;
    int f = s / NSP;
    size_t src = ((size_t)(b*Ss + s)*Ff + f)*(Dd/4) + c4;
    XDH[idx] = XH[src];
    XDL[idx] = XL[src];
}

// ============================================================
// traj: per token — logits from x·m + q2·bk2, softmax over F,
// xw[h] = sum_f attn*x_f -> bf16 planes
// 128 threads / token; warp w handles heads 3w..3w+2.
// ============================================================
__global__ __launch_bounds__(128) void traj_kernel(
    const __nv_bfloat16* __restrict__ xh, const __nv_bfloat16* __restrict__ xl,
    const __nv_bfloat16* __restrict__ q2h, const __nv_bfloat16* __restrict__ q2l,
    const float* __restrict__ M_, const float* __restrict__ bpkv,
    __nv_bfloat16* __restrict__ xwh, __nv_bfloat16* __restrict__ xwl)
{
    __shared__ float xs[Ff][768];
    __shared__ float bq[Hh];
    const int t = blockIdx.x;
    const int tid = threadIdx.x;
    const int wid = tid >> 5, lane = tid & 31;

    // load x fp32 = hi + lo
    {
        const uint4* ph = (const uint4*)(xh + (size_t)t*Ff*768);
        const uint4* pl = (const uint4*)(xl + (size_t)t*Ff*768);
        for (int i = tid; i < 768; i += 128) {   // 768 chunks of 8 bf16
            uint4 vh = ph[i], vl = pl[i];
            int f = i >> 6, j = (i & 63) * 8;    // 768/8 = 96... (i*8)/768: careful
            f = (i * 8) / 768; j = (i * 8) % 768;
            const uint32_t* wh = (const uint32_t*)&vh;
            const uint32_t* wl = (const uint32_t*)&vl;
#pragma unroll
            for (int w = 0; w < 4; w++) {
                float2 fh = __bfloat1622float2(*(const __nv_bfloat162*)&wh[w]);
                float2 fl = __bfloat1622float2(*(const __nv_bfloat162*)&wl[w]);
                xs[f][j + w*2 + 0] = fh.x + fl.x;
                xs[f][j + w*2 + 1] = fh.y + fl.y;
            }
        }
    }
    // bias term bq[h] = q2[t,h]·bk2[h]
#pragma unroll
    for (int hh = 0; hh < 3; hh++) {
        int h = wid * 3 + hh;
        int d0 = h*64 + lane;
        float qa = __bfloat162float(q2h[(size_t)t*768 + d0])      + __bfloat162float(q2l[(size_t)t*768 + d0]);
        float qb = __bfloat162float(q2h[(size_t)t*768 + d0 + 32]) + __bfloat162float(q2l[(size_t)t*768 + d0 + 32]);
        float acc = qa * bpkv[d0] + qb * bpkv[d0 + 32];
#pragma unroll
        for (int o = 16; o > 0; o >>= 1) acc += __shfl_xor_sync(0xffffffffu, acc, o);
        if (lane == 0) bq[h] = acc;
    }
    __syncthreads();

#pragma unroll
    for (int hh = 0; hh < 3; hh++) {
        int h = wid * 3 + hh;
        const float* mh = M_ + (size_t)t*(Hh*768) + (size_t)h*768;
        float acc[Ff];
#pragma unroll
        for (int f = 0; f < Ff; f++) acc[f] = 0.f;
        for (int js = 0; js < 24; js++) {
            int j = js*32 + lane;
            float mv = mh[j];
#pragma unroll
            for (int f = 0; f < Ff; f++) acc[f] += xs[f][j] * mv;
        }
        float lg[Ff];
#pragma unroll
        for (int f = 0; f < Ff; f++) {
            float s = acc[f];
#pragma unroll
            for (int o = 16; o > 0; o >>= 1) s += __shfl_xor_sync(0xffffffffu, s, o);
            lg[f] = SCALE * (s + bq[h]);
        }
        float mm = lg[0];
#pragma unroll
        for (int f = 1; f < Ff; f++) mm = fmaxf(mm, lg[f]);
        float attn[Ff], sum = 0.f;
#pragma unroll
        for (int f = 0; f < Ff; f++) { attn[f] = __expf(lg[f] - mm); sum += attn[f]; }
        float inv = 1.f / sum;
#pragma unroll
        for (int f = 0; f < Ff; f++) attn[f] *= inv;

        size_t base = (size_t)t*(Hh*768) + (size_t)h*768;
        for (int i = 0; i < 12; i++) {
            int j0 = i*64 + lane*2;
            float a0 = 0.f, a1 = 0.f;
#pragma unroll
            for (int f = 0; f < Ff; f++) {
                a0 += attn[f] * xs[f][j0];
                a1 += attn[f] * xs[f][j0 + 1];
            }
            uint32_t hb, lb;
            split2(a0, a1, hb, lb);
            *(uint32_t*)&xwh[base + j0] = hb;
            *(uint32_t*)&xwl[base + j0] = lb;
        }
    }
}

// ============================================================
// launch
// ============================================================
extern "C" void kernel_launch(void* const* d_in, const int* in_sizes, int n_in,
                              void* d_out, int out_size)
{
    const float* query = (const float*)d_in[0];
    const float* key_t = (const float*)d_in[1];
    const float* value = (const float*)d_in[2];
    const float* Wq   = (const float*)d_in[3];
    const float* bq   = (const float*)d_in[4];
    const float* Wk   = (const float*)d_in[5];
    const float* bk   = (const float*)d_in[6];
    const float* Wv   = (const float*)d_in[7];
    const float* bv   = (const float*)d_in[8];
    const float* Wpq  = (const float*)d_in[9];
    const float* bpq  = (const float*)d_in[10];
    const float* Wpkv = (const float*)d_in[11];
    const float* bpkv = (const float*)d_in[12];
    const float* Wp   = (const float*)d_in[13];
    const float* bp   = (const float*)d_in[14];

    float* out = (float*)d_out;            // (B, S, D)
    float* sa  = out + BSD;                // (B*H, S, F, n)

    float *mbuf, *zerob;
    __nv_bfloat16 *wth, *wtl, *wk2h, *wk2l;
    __nv_bfloat16 *inqh, *inql, *inkh, *inkl, *invh, *invl;
    __nv_bfloat16 *qph, *qpl, *kph, *kpl, *vph, *vpl;
    __nv_bfloat16 *xh, *xl, *xdh, *xdl, *q2h, *q2l, *xwh, *xwl, *t2h, *t2l;
    cudaGetSymbolAddress((void**)&mbuf, g_m);
    cudaGetSymbolAddress((void**)&zerob, g_zerob);
    cudaGetSymbolAddress((void**)&wth, g_wth);
    cudaGetSymbolAddress((void**)&wtl, g_wtl);
    cudaGetSymbolAddress((void**)&wk2h, g_wk2h);
    cudaGetSymbolAddress((void**)&wk2l, g_wk2l);
    cudaGetSymbolAddress((void**)&inqh, g_inqh);
    cudaGetSymbolAddress((void**)&inql, g_inql);
    cudaGetSymbolAddress((void**)&inkh, g_inkh);
    cudaGetSymbolAddress((void**)&inkl, g_inkl);
    cudaGetSymbolAddress((void**)&invh, g_invh);
    cudaGetSymbolAddress((void**)&invl, g_invl);
    cudaGetSymbolAddress((void**)&qph, g_qph);
    cudaGetSymbolAddress((void**)&qpl, g_qpl);
    cudaGetSymbolAddress((void**)&kph, g_kph);
    cudaGetSymbolAddress((void**)&kpl, g_kpl);
    cudaGetSymbolAddress((void**)&vph, g_vph);
    cudaGetSymbolAddress((void**)&vpl, g_vpl);
    cudaGetSymbolAddress((void**)&xh,  g_xh);
    cudaGetSymbolAddress((void**)&xl,  g_xl);
    cudaGetSymbolAddress((void**)&xdh, g_xdh);
    cudaGetSymbolAddress((void**)&xdl, g_xdl);
    cudaGetSymbolAddress((void**)&q2h, g_q2h);
    cudaGetSymbolAddress((void**)&q2l, g_q2l);
    cudaGetSymbolAddress((void**)&xwh, g_xwh);
    cudaGetSymbolAddress((void**)&xwl, g_xwl);
    cudaGetSymbolAddress((void**)&t2h, g_t2h);
    cudaGetSymbolAddress((void**)&t2l, g_t2l);

    cudaFuncSetAttribute(stage1_mma_kernel,
                         cudaFuncAttributeMaxDynamicSharedMemorySize, S1_SMEM);
    cudaFuncSetAttribute(gemm_tpl<0,128>,
                         cudaFuncAttributeMaxDynamicSharedMemorySize, SMEM_128);
    cudaFuncSetAttribute(gemm_tpl<1,128>,
                         cudaFuncAttributeMaxDynamicSharedMemorySize, SMEM_128);
    cudaFuncSetAttribute(gemm_tpl<1,64>,
                         cudaFuncAttributeMaxDynamicSharedMemorySize, SMEM_64);

    // ---- weight prep ----
    dim3 wb(32, 8);
    wtrans_kernel<<<dim3(24,24), wb>>>(Wq,   wth+OFF_WQ,   wtl+OFF_WQ,   768, 768);
    wtrans_kernel<<<dim3(24,24), wb>>>(Wk,   wth+OFF_WK,   wtl+OFF_WK,   768, 768);
    wtrans_kernel<<<dim3(24,24), wb>>>(Wv,   wth+OFF_WV,   wtl+OFF_WV,   768, 768);
    wtrans_kernel<<<dim3(24,24), wb>>>(Wpq,  wth+OFF_WPQ,  wtl+OFF_WPQ,  768, 768);
    wtrans_kernel<<<dim3(24,24), wb>>>(Wp,   wth+OFF_WP,   wtl+OFF_WP,   768, 768);
    wtrans_kernel<<<dim3(48,24), wb>>>(Wpkv, wth+OFF_WPKV, wtl+OFF_WPKV, 768, 1536);
    splitwk2_kernel<<<(768*192 + 255)/256, 256>>>(Wpkv, wk2h, wk2l);

    // ---- split fp32 inputs to bf16 planes ----
    int n4 = BSD/4, sg = (n4 + 255)/256;
    split_kernel<<<sg, 256>>>((const float4*)query, (uint2*)inqh, (uint2*)inql, n4);
    split_kernel<<<sg, 256>>>((const float4*)key_t, (uint2*)inkh, (uint2*)inkl, n4);
    split_kernel<<<sg, 256>>>((const float4*)value, (uint2*)invh, (uint2*)invl, n4);

    dim3 gP(6, 25, 1);

    // projections -> bf16 hi/lo planes
    gemm_tpl<1,128><<<gP, 256, SMEM_128>>>(inqh, inql, 768, 0, wth+OFF_WQ, wtl+OFF_WQ, 768, 0,
        bq, 0, nullptr, qph, qpl, 768, 0, BS, 768);
    gemm_tpl<1,128><<<gP, 256, SMEM_128>>>(inkh, inkl, 768, 0, wth+OFF_WK, wtl+OFF_WK, 768, 0,
        bk, 0, nullptr, kph, kpl, 768, 0, BS, 768);
    gemm_tpl<1,128><<<gP, 256, SMEM_128>>>(invh, invl, 768, 0, wth+OFF_WV, wtl+OFF_WV, 768, 0,
        bv, 0, nullptr, vph, vpl, 768, 0, BS, 768);

    stage1_mma_kernel<<<dim3(13, Ff, Bb*Hh), 256, S1_SMEM>>>(
        qph, qpl, kph, kpl, vph, vpl, xh, xl, sa);

    diag_kernel<<<(BSD/4 + 255)/256, 256>>>(
        (const uint2*)xh, (const uint2*)xl, (uint2*)xdh, (uint2*)xdl);

    // q2 = xd @ Wpq + bpq  (split output)
    gemm_tpl<1,128><<<gP, 256, SMEM_128>>>(xdh, xdl, 768, 0, wth+OFF_WPQ, wtl+OFF_WPQ, 768, 0,
        bpq, 0, nullptr, q2h, q2l, 768, 0, BS, 768);

    // m[t,h,:] = Wk2[:,hslice] @ q2_h : per-head GEMM M=BS, N=768, K=64
    gemm_tpl<0,128><<<dim3(6, 25, 12), 256, SMEM_128>>>(
        q2h, q2l, 768, 64,          // A = q2 head slice
        wk2h, wk2l, 768, 64,        // B = Wpkv rows, head cols
        zerob, 0,
        mbuf, nullptr, nullptr, Hh*768, 768,
        BS, 64);

    // logits + softmax + xw
    traj_kernel<<<BS, 128>>>(xh, xl, q2h, q2l, mbuf, bpkv, xwh, xwl);

    // o_h = xw_h @ Wv2[:,hslice] + bv2_h : per-head GEMM M=BS, N=64, K=768 -> t2 planes
    gemm_tpl<1,64><<<dim3(1, 25, 12), 256, SMEM_64>>>(
        xwh, xwl, Hh*768, 768,                                  // A = xw head slice
        wth + OFF_WPKV + (size_t)768*768, wtl + OFF_WPKV + (size_t)768*768, 768, (long)64*768,
        bpkv + 768, 64,
        nullptr, t2h, t2l, 768, 64,
        BS, 768);

    // out = t2 @ Wp + bp
    gemm_tpl<0,128><<<gP, 256, SMEM_128>>>(t2h, t2l, 768, 0, wth+OFF_WP, wtl+OFF_WP, 768, 0,
        bp, 0, out, nullptr, nullptr, 768, 0, BS, 768);
}